// round 3
// baseline (speedup 1.0000x reference)
#include <cuda_runtime.h>

// Problem constants
#define BB     4
#define S_LEN  2048
#define T_LEN  2048
#define HDIM   1024
#define ADIM   1024
#define NHEAD  16
#define HEADD  64
#define MROWS  8192   // B*S == B*T

// Scratch (device globals; no allocations allowed)
__device__ float g_Q[MROWS * ADIM];
__device__ float g_K[MROWS * ADIM];
__device__ float g_V[MROWS * ADIM];
__device__ float g_O[MROWS * ADIM];

// ---------------------------------------------------------------------------
// SGEMM: C[M,N] = A[M,K] @ B[K,N] + bias[N]   (all row-major, fp32)
// 128x128 block tile, BK=8, 256 threads, 8x8 per thread.
// ---------------------------------------------------------------------------
__global__ __launch_bounds__(256) void sgemm_bias_kernel(
    const float* __restrict__ A, const float* __restrict__ Bm,
    const float* __restrict__ bias, float* __restrict__ C,
    int M, int N, int K)
{
    __shared__ float As[8][128];   // transposed: As[k][m]
    __shared__ float Bs[8][128];   // Bs[k][n]

    const int bx = blockIdx.x;     // N tile
    const int by = blockIdx.y;     // M tile
    const int tid = threadIdx.x;

    const int arow = tid >> 1;           // 0..127
    const int acol = (tid & 1) << 2;     // 0 or 4
    const int brow = tid >> 5;           // 0..7
    const int bcol = (tid & 31) << 2;    // 0..124

    const int ty = tid >> 4;             // 0..15
    const int tx = tid & 15;             // 0..15

    const float* Ap = A + (size_t)(by * 128) * K;
    const float* Bp = Bm + (size_t)(bx * 128);

    float acc[8][8];
#pragma unroll
    for (int i = 0; i < 8; i++)
#pragma unroll
        for (int j = 0; j < 8; j++) acc[i][j] = 0.0f;

    for (int k0 = 0; k0 < K; k0 += 8) {
        float4 av = *(const float4*)(Ap + (size_t)arow * K + k0 + acol);
        As[acol + 0][arow] = av.x;
        As[acol + 1][arow] = av.y;
        As[acol + 2][arow] = av.z;
        As[acol + 3][arow] = av.w;
        float4 bv = *(const float4*)(Bp + (size_t)(k0 + brow) * N + bcol);
        *(float4*)&Bs[brow][bcol] = bv;
        __syncthreads();

#pragma unroll
        for (int k = 0; k < 8; k++) {
            float4 a0 = *(const float4*)&As[k][ty * 8];
            float4 a1 = *(const float4*)&As[k][ty * 8 + 4];
            float4 b0 = *(const float4*)&Bs[k][tx * 8];
            float4 b1 = *(const float4*)&Bs[k][tx * 8 + 4];
            float af[8] = {a0.x, a0.y, a0.z, a0.w, a1.x, a1.y, a1.z, a1.w};
            float bf[8] = {b0.x, b0.y, b0.z, b0.w, b1.x, b1.y, b1.z, b1.w};
#pragma unroll
            for (int i = 0; i < 8; i++)
#pragma unroll
                for (int j = 0; j < 8; j++)
                    acc[i][j] = fmaf(af[i], bf[j], acc[i][j]);
        }
        __syncthreads();
    }

    // epilogue + bias
#pragma unroll
    for (int i = 0; i < 8; i++) {
        int row = by * 128 + ty * 8 + i;
#pragma unroll
        for (int j = 0; j < 8; j += 4) {
            int col = bx * 128 + tx * 8 + j;
            float4 o;
            o.x = acc[i][j + 0] + bias[col + 0];
            o.y = acc[i][j + 1] + bias[col + 1];
            o.z = acc[i][j + 2] + bias[col + 2];
            o.w = acc[i][j + 3] + bias[col + 3];
            *(float4*)(C + (size_t)row * N + col) = o;
        }
    }
}

// ---------------------------------------------------------------------------
// Flash attention (fp32, online softmax).
// Grid: (S/64, NH, B). Block: 256 threads (16x16), each thread 4 rows x 4 cols.
// Q/K/V laid out as [B*len, ADIM] with head h occupying cols h*64..h*64+63.
// Mask is int32 (bool promoted by harness). Exact reference math:
//   score = m ? qk/sqrt(64) : -100000.
// Smem: Qs, Ks (reused for P), Vs each 64x65 fp32 -> 49920 bytes dynamic.
// ---------------------------------------------------------------------------
__global__ __launch_bounds__(256) void flash_attn_kernel(
    const float* __restrict__ Q, const float* __restrict__ K,
    const float* __restrict__ V, const int* __restrict__ mask,
    float* __restrict__ O)
{
    extern __shared__ float sm[];
    float* Qs = sm;               // 64*65
    float* Ks = sm + 64 * 65;     // 64*65 (reused to hold P)
    float* Vs = sm + 2 * 64 * 65; // 64*65

    const int s0 = blockIdx.x * 64;
    const int h  = blockIdx.y;
    const int b  = blockIdx.z;
    const int tid = threadIdx.x;
    const int ty = tid >> 4;      // 0..15 -> rows ty*4..ty*4+3
    const int tx = tid & 15;      // 0..15 -> cols tx*4..tx*4+3

    const float* Qb = Q + ((size_t)(b * S_LEN + s0)) * ADIM + h * HEADD;
    const float* Kb = K + ((size_t)b * T_LEN) * ADIM + h * HEADD;
    const float* Vb = V + ((size_t)b * T_LEN) * ADIM + h * HEADD;
    const int* mb = mask + (size_t)b * T_LEN;

    // Load Q tile, pre-scaled by 1/sqrt(64) so masking math stays exact.
#pragma unroll
    for (int i = 0; i < 4; i++) {
        int idx = tid + i * 256;
        int r = idx >> 4, c = (idx & 15) << 2;
        float4 v = *(const float4*)(Qb + (size_t)r * ADIM + c);
        Qs[r * 65 + c + 0] = v.x * 0.125f;
        Qs[r * 65 + c + 1] = v.y * 0.125f;
        Qs[r * 65 + c + 2] = v.z * 0.125f;
        Qs[r * 65 + c + 3] = v.w * 0.125f;
    }

    float m_i[4], l_i[4], acc[4][4];
#pragma unroll
    for (int i = 0; i < 4; i++) {
        m_i[i] = -1e30f;
        l_i[i] = 0.0f;
#pragma unroll
        for (int j = 0; j < 4; j++) acc[i][j] = 0.0f;
    }

    for (int t0 = 0; t0 < T_LEN; t0 += 64) {
        // Load K and V tiles
#pragma unroll
        for (int i = 0; i < 4; i++) {
            int idx = tid + i * 256;
            int r = idx >> 4, c = (idx & 15) << 2;
            float4 kv = *(const float4*)(Kb + (size_t)(t0 + r) * ADIM + c);
            Ks[r * 65 + c + 0] = kv.x;
            Ks[r * 65 + c + 1] = kv.y;
            Ks[r * 65 + c + 2] = kv.z;
            Ks[r * 65 + c + 3] = kv.w;
            float4 vv = *(const float4*)(Vb + (size_t)(t0 + r) * ADIM + c);
            Vs[r * 65 + c + 0] = vv.x;
            Vs[r * 65 + c + 1] = vv.y;
            Vs[r * 65 + c + 2] = vv.z;
            Vs[r * 65 + c + 3] = vv.w;
        }
        __syncthreads();

        // Scores: sc[i][j] = sum_d Qs[row_i][d] * Ks[col_j][d]  (Q pre-scaled)
        float sc[4][4];
#pragma unroll
        for (int i = 0; i < 4; i++)
#pragma unroll
            for (int j = 0; j < 4; j++) sc[i][j] = 0.0f;

#pragma unroll 8
        for (int d = 0; d < 64; d++) {
            float q[4], kk[4];
#pragma unroll
            for (int i = 0; i < 4; i++) q[i] = Qs[(ty * 4 + i) * 65 + d];
#pragma unroll
            for (int j = 0; j < 4; j++) kk[j] = Ks[(tx * 4 + j) * 65 + d];
#pragma unroll
            for (int i = 0; i < 4; i++)
#pragma unroll
                for (int j = 0; j < 4; j++)
                    sc[i][j] = fmaf(q[i], kk[j], sc[i][j]);
        }

        // Mask (exact reference: masked -> -100000). mask is int32 0/1.
#pragma unroll
        for (int j = 0; j < 4; j++) {
            if (mb[t0 + tx * 4 + j] == 0) {
#pragma unroll
                for (int i = 0; i < 4; i++) sc[i][j] = -100000.0f;
            }
        }

        // Online softmax update (row reduce across 16 lanes of segment)
#pragma unroll
        for (int i = 0; i < 4; i++) {
            float mx = fmaxf(fmaxf(sc[i][0], sc[i][1]), fmaxf(sc[i][2], sc[i][3]));
#pragma unroll
            for (int o = 8; o >= 1; o >>= 1)
                mx = fmaxf(mx, __shfl_xor_sync(0xffffffffu, mx, o, 16));
            float mnew = fmaxf(m_i[i], mx);
            float p0 = __expf(sc[i][0] - mnew);
            float p1 = __expf(sc[i][1] - mnew);
            float p2 = __expf(sc[i][2] - mnew);
            float p3 = __expf(sc[i][3] - mnew);
            sc[i][0] = p0; sc[i][1] = p1; sc[i][2] = p2; sc[i][3] = p3;
            float ls = p0 + p1 + p2 + p3;
#pragma unroll
            for (int o = 8; o >= 1; o >>= 1)
                ls += __shfl_xor_sync(0xffffffffu, ls, o, 16);
            float alpha = __expf(m_i[i] - mnew);
            l_i[i] = l_i[i] * alpha + ls;
            m_i[i] = mnew;
#pragma unroll
            for (int j = 0; j < 4; j++) acc[i][j] *= alpha;
        }

        __syncthreads();  // everyone done reading Ks before overwriting with P

        // Write P into Ks buffer
#pragma unroll
        for (int i = 0; i < 4; i++)
#pragma unroll
            for (int j = 0; j < 4; j++)
                Ks[(ty * 4 + i) * 65 + tx * 4 + j] = sc[i][j];
        __syncthreads();

        // O += P @ V : acc[i][j] over d-cols tx*4+j
#pragma unroll 8
        for (int c = 0; c < 64; c++) {
            float p[4], vv[4];
#pragma unroll
            for (int i = 0; i < 4; i++) p[i] = Ks[(ty * 4 + i) * 65 + c];
#pragma unroll
            for (int j = 0; j < 4; j++) vv[j] = Vs[c * 65 + tx * 4 + j];
#pragma unroll
            for (int i = 0; i < 4; i++)
#pragma unroll
                for (int j = 0; j < 4; j++)
                    acc[i][j] = fmaf(p[i], vv[j], acc[i][j]);
        }
        __syncthreads();  // before next tile load overwrites Ks/Vs
    }

    // Normalize and write O in [B*S, ADIM] layout (head h at cols h*64..)
#pragma unroll
    for (int i = 0; i < 4; i++) {
        float inv = 1.0f / l_i[i];
        int row = s0 + ty * 4 + i;
        float4 o;
        o.x = acc[i][0] * inv;
        o.y = acc[i][1] * inv;
        o.z = acc[i][2] * inv;
        o.w = acc[i][3] * inv;
        *(float4*)(O + ((size_t)(b * S_LEN + row)) * ADIM + h * HEADD + tx * 4) = o;
    }
}

// ---------------------------------------------------------------------------
// Launch
// ---------------------------------------------------------------------------
extern "C" void kernel_launch(void* const* d_in, const int* in_sizes, int n_in,
                              void* d_out, int out_size)
{
    const float* x  = (const float*)d_in[0];
    const float* y  = (const float*)d_in[1];
    const int*   mask = (const int*)d_in[2];   // bool promoted to int32
    const float* wq = (const float*)d_in[3];
    const float* bq = (const float*)d_in[4];
    const float* wk = (const float*)d_in[5];
    const float* bk = (const float*)d_in[6];
    const float* wv = (const float*)d_in[7];
    const float* bv = (const float*)d_in[8];
    const float* wo = (const float*)d_in[9];
    const float* bo = (const float*)d_in[10];
    float* out = (float*)d_out;

    float *Qp, *Kp, *Vp, *Op;
    cudaGetSymbolAddress((void**)&Qp, g_Q);
    cudaGetSymbolAddress((void**)&Kp, g_K);
    cudaGetSymbolAddress((void**)&Vp, g_V);
    cudaGetSymbolAddress((void**)&Op, g_O);

    const int attn_smem = 3 * 64 * 65 * 4;  // 49920 bytes
    cudaFuncSetAttribute(flash_attn_kernel,
                         cudaFuncAttributeMaxDynamicSharedMemorySize, attn_smem);

    dim3 gs(ADIM / 128, MROWS / 128);   // (8, 64)
    dim3 bs(256);

    // Projections
    sgemm_bias_kernel<<<gs, bs>>>(x, wq, bq, Qp, MROWS, ADIM, HDIM);
    sgemm_bias_kernel<<<gs, bs>>>(y, wk, bk, Kp, MROWS, ADIM, HDIM);
    sgemm_bias_kernel<<<gs, bs>>>(y, wv, bv, Vp, MROWS, ADIM, HDIM);

    // Attention
    dim3 ga(S_LEN / 64, NHEAD, BB);     // (32, 16, 4)
    flash_attn_kernel<<<ga, 256, attn_smem>>>(Qp, Kp, Vp, mask, Op);

    // Output projection
    sgemm_bias_kernel<<<gs, bs>>>(Op, wo, bo, out, MROWS, HDIM, ADIM);
}

// round 5
// speedup vs baseline: 1.3607x; 1.3607x over previous
#include <cuda_runtime.h>
#include <cuda_bf16.h>
#include <cstdint>

// Problem constants
#define BB     4
#define S_LEN  2048
#define T_LEN  2048
#define HDIM   1024
#define ADIM   1024
#define NHEAD  16
#define HEADD  64
#define MROWS  8192   // B*S == B*T

// ---------------------------------------------------------------------------
// Device scratch (no allocations allowed)
// ---------------------------------------------------------------------------
__device__ float g_Q[MROWS * ADIM];
__device__ float g_K[MROWS * ADIM];
__device__ float g_V[MROWS * ADIM];
__device__ float g_O[MROWS * ADIM];

// bf16 hi/lo splits of activations
__device__ __align__(16) __nv_bfloat16 g_xh[MROWS * HDIM];
__device__ __align__(16) __nv_bfloat16 g_xl[MROWS * HDIM];
__device__ __align__(16) __nv_bfloat16 g_yh[MROWS * HDIM];
__device__ __align__(16) __nv_bfloat16 g_yl[MROWS * HDIM];
__device__ __align__(16) __nv_bfloat16 g_oh[MROWS * ADIM];
__device__ __align__(16) __nv_bfloat16 g_ol[MROWS * ADIM];
// bf16 hi/lo transposed weights: Bt[n][k] = W[k][n]
__device__ __align__(16) __nv_bfloat16 g_wqh[ADIM * HDIM];
__device__ __align__(16) __nv_bfloat16 g_wql[ADIM * HDIM];
__device__ __align__(16) __nv_bfloat16 g_wkh[ADIM * HDIM];
__device__ __align__(16) __nv_bfloat16 g_wkl[ADIM * HDIM];
__device__ __align__(16) __nv_bfloat16 g_wvh[ADIM * HDIM];
__device__ __align__(16) __nv_bfloat16 g_wvl[ADIM * HDIM];
__device__ __align__(16) __nv_bfloat16 g_woh[HDIM * ADIM];
__device__ __align__(16) __nv_bfloat16 g_wol[HDIM * ADIM];

// ---------------------------------------------------------------------------
// PTX helpers (sm_80-era only: cp.async, ldmatrix, mma.sync — legal on sm_103)
// ---------------------------------------------------------------------------
__device__ __forceinline__ uint32_t smem_u32(const void* p) {
    uint32_t a;
    asm("{ .reg .u64 t; cvta.to.shared.u64 t, %1; cvt.u32.u64 %0, t; }" : "=r"(a) : "l"(p));
    return a;
}

#define CP_ASYNC16(smem, gptr) \
    asm volatile("cp.async.cg.shared.global [%0], [%1], 16;" \
                 :: "r"((uint32_t)(smem)), "l"(gptr) : "memory")
#define CP_ASYNC_COMMIT() asm volatile("cp.async.commit_group;" ::: "memory")
#define CP_ASYNC_WAIT0()  asm volatile("cp.async.wait_group 0;" ::: "memory")
#define CP_ASYNC_WAIT1()  asm volatile("cp.async.wait_group 1;" ::: "memory")

#define LDSM_X4(r0, r1, r2, r3, a) \
    asm volatile("ldmatrix.sync.aligned.m8n8.x4.shared.b16 {%0,%1,%2,%3}, [%4];" \
                 : "=r"(r0), "=r"(r1), "=r"(r2), "=r"(r3) : "r"(a))
#define LDSM_X2(r0, r1, a) \
    asm volatile("ldmatrix.sync.aligned.m8n8.x2.shared.b16 {%0,%1}, [%2];" \
                 : "=r"(r0), "=r"(r1) : "r"(a))

#define MMA_BF16(d, a, b) \
    asm volatile("mma.sync.aligned.m16n8k16.row.col.f32.bf16.bf16.f32 " \
                 "{%0,%1,%2,%3}, {%4,%5,%6,%7}, {%8,%9}, {%0,%1,%2,%3};" \
                 : "+f"((d)[0]), "+f"((d)[1]), "+f"((d)[2]), "+f"((d)[3]) \
                 : "r"((a)[0]), "r"((a)[1]), "r"((a)[2]), "r"((a)[3]), \
                   "r"((b)[0]), "r"((b)[1]))

// ---------------------------------------------------------------------------
// Split fp32 -> bf16 hi/lo
// ---------------------------------------------------------------------------
__global__ __launch_bounds__(256) void split_kernel(
    const float4* __restrict__ in, uint2* __restrict__ hi, uint2* __restrict__ lo, int n4)
{
    int i = blockIdx.x * 256 + threadIdx.x;
    if (i >= n4) return;
    float4 v = in[i];
    __nv_bfloat16 h0 = __float2bfloat16(v.x), h1 = __float2bfloat16(v.y);
    __nv_bfloat16 h2 = __float2bfloat16(v.z), h3 = __float2bfloat16(v.w);
    __nv_bfloat16 l0 = __float2bfloat16(v.x - __bfloat162float(h0));
    __nv_bfloat16 l1 = __float2bfloat16(v.y - __bfloat162float(h1));
    __nv_bfloat16 l2 = __float2bfloat16(v.z - __bfloat162float(h2));
    __nv_bfloat16 l3 = __float2bfloat16(v.w - __bfloat162float(h3));
    uint2 hw, lw;
    hw.x = (uint32_t)__bfloat16_as_ushort(h0) | ((uint32_t)__bfloat16_as_ushort(h1) << 16);
    hw.y = (uint32_t)__bfloat16_as_ushort(h2) | ((uint32_t)__bfloat16_as_ushort(h3) << 16);
    lw.x = (uint32_t)__bfloat16_as_ushort(l0) | ((uint32_t)__bfloat16_as_ushort(l1) << 16);
    lw.y = (uint32_t)__bfloat16_as_ushort(l2) | ((uint32_t)__bfloat16_as_ushort(l3) << 16);
    hi[i] = hw;
    lo[i] = lw;
}

// ---------------------------------------------------------------------------
// Transpose + split weights: W[1024][1024] fp32 -> Bt_hi/lo[n][k] bf16
// ---------------------------------------------------------------------------
__global__ __launch_bounds__(256) void transpose_split_kernel(
    const float* __restrict__ W, __nv_bfloat16* __restrict__ th, __nv_bfloat16* __restrict__ tl)
{
    __shared__ float t[32][33];
    int tx = threadIdx.x, ty = threadIdx.y;
    int n0 = blockIdx.x * 32, k0 = blockIdx.y * 32;
#pragma unroll
    for (int i = 0; i < 32; i += 8)
        t[ty + i][tx] = W[(size_t)(k0 + ty + i) * 1024 + n0 + tx];
    __syncthreads();
#pragma unroll
    for (int i = 0; i < 32; i += 8) {
        float v = t[tx][ty + i];  // = W[k0+tx][n0+ty+i]
        __nv_bfloat16 h = __float2bfloat16(v);
        __nv_bfloat16 l = __float2bfloat16(v - __bfloat162float(h));
        size_t o = (size_t)(n0 + ty + i) * 1024 + k0 + tx;
        th[o] = h;
        tl[o] = l;
    }
}

// ---------------------------------------------------------------------------
// mma.sync split-bf16 GEMM: C[8192,1024] = A[8192,1024] @ W + bias
// A as bf16 hi/lo row-major [m][k]; W as Bt hi/lo [n][k] (K-contiguous).
// CTA tile 128x128, 8 warps (2x4), warp tile 64x32, BK=32, double-buffered.
// ---------------------------------------------------------------------------
#define G_K     1024
#define G_N     1024
#define BKC     32
#define PAD_B   80                 // bytes per smem row (32 bf16 + 8 pad)
#define MAT_B   (128 * PAD_B)      // 10240 bytes per matrix per stage
#define OFF_AH  0
#define OFF_AL  (1 * MAT_B)
#define OFF_BH  (2 * MAT_B)
#define OFF_BL  (3 * MAT_B)
#define STAGE_B (4 * MAT_B)        // 40960 bytes
#define GEMM_DSMEM (2 * STAGE_B)   // 81920 bytes

__device__ __forceinline__ void gemm_load_stage(
    uint32_t sb, const __nv_bfloat16* __restrict__ Ah, const __nv_bfloat16* __restrict__ Al,
    const __nv_bfloat16* __restrict__ Bh, const __nv_bfloat16* __restrict__ Bl,
    int m0, int n0, int k0, int tid)
{
#pragma unroll
    for (int i = 0; i < 2; i++) {
        int idx = tid + i * 256;       // 0..511
        int r = idx >> 2, sg = idx & 3;
        uint32_t so = (uint32_t)(r * PAD_B + sg * 16);
        size_t ga = (size_t)(m0 + r) * G_K + k0 + sg * 8;
        size_t gb = (size_t)(n0 + r) * G_K + k0 + sg * 8;
        CP_ASYNC16(sb + OFF_AH + so, Ah + ga);
        CP_ASYNC16(sb + OFF_AL + so, Al + ga);
        CP_ASYNC16(sb + OFF_BH + so, Bh + gb);
        CP_ASYNC16(sb + OFF_BL + so, Bl + gb);
    }
}

__global__ __launch_bounds__(256) void gemm_mma_kernel(
    const __nv_bfloat16* __restrict__ Ah, const __nv_bfloat16* __restrict__ Al,
    const __nv_bfloat16* __restrict__ Bh, const __nv_bfloat16* __restrict__ Bl,
    const float* __restrict__ bias, float* __restrict__ C)
{
    extern __shared__ __align__(16) char dsm[];
    const uint32_t sm0 = smem_u32(dsm);
    const int tid = threadIdx.x;
    const int wid = tid >> 5;
    const int lane = tid & 31;
    const int wm = wid >> 2;          // 0..1
    const int wn = wid & 3;           // 0..3
    const int m0 = blockIdx.y * 128;
    const int n0 = blockIdx.x * 128;

    float acc[4][4][4];
#pragma unroll
    for (int i = 0; i < 4; i++)
#pragma unroll
        for (int j = 0; j < 4; j++)
#pragma unroll
            for (int c = 0; c < 4; c++) acc[i][j][c] = 0.0f;

    // Precompute intra-tile ldmatrix lane offsets
    const int t4 = lane >> 3;                                  // tile id for x4
    const uint32_t a_lane_off = (uint32_t)(((lane & 7) + ((t4 & 1) << 3)) * PAD_B
                                           + ((t4 >> 1) << 3) * 2);
    const int li = lane & 15;                                  // for x2
    const uint32_t b_lane_off = (uint32_t)((li & 7) * PAD_B + ((li >> 3) << 3) * 2);

    gemm_load_stage(sm0, Ah, Al, Bh, Bl, m0, n0, 0, tid);
    CP_ASYNC_COMMIT();

    const int NCH = G_K / BKC;   // 32
    for (int kc = 0; kc < NCH; kc++) {
        const uint32_t sb = sm0 + (kc & 1) * STAGE_B;
        if (kc + 1 < NCH) {
            gemm_load_stage(sm0 + ((kc + 1) & 1) * STAGE_B, Ah, Al, Bh, Bl,
                            m0, n0, (kc + 1) * BKC, tid);
            CP_ASYNC_COMMIT();
            CP_ASYNC_WAIT1();
        } else {
            CP_ASYNC_WAIT0();
        }
        __syncthreads();

#pragma unroll
        for (int ks = 0; ks < 2; ks++) {
            const uint32_t kb = (uint32_t)(ks * 16 * 2);  // byte offset of k-step
            uint32_t bh[4][2], bl[4][2];
#pragma unroll
            for (int nf = 0; nf < 4; nf++) {
                uint32_t base = (uint32_t)((wn * 32 + nf * 8) * PAD_B) + kb + b_lane_off;
                LDSM_X2(bh[nf][0], bh[nf][1], sb + OFF_BH + base);
                LDSM_X2(bl[nf][0], bl[nf][1], sb + OFF_BL + base);
            }
#pragma unroll
            for (int mf = 0; mf < 4; mf++) {
                uint32_t base = (uint32_t)((wm * 64 + mf * 16) * PAD_B) + kb + a_lane_off;
                uint32_t ah[4], al[4];
                LDSM_X4(ah[0], ah[1], ah[2], ah[3], sb + OFF_AH + base);
                LDSM_X4(al[0], al[1], al[2], al[3], sb + OFF_AL + base);
#pragma unroll
                for (int nf = 0; nf < 4; nf++) {
                    MMA_BF16(acc[mf][nf], ah, bh[nf]);
                    MMA_BF16(acc[mf][nf], ah, bl[nf]);
                    MMA_BF16(acc[mf][nf], al, bh[nf]);
                }
            }
        }
        __syncthreads();
    }

    // Epilogue: direct stores + bias
#pragma unroll
    for (int mf = 0; mf < 4; mf++) {
        int row0 = m0 + wm * 64 + mf * 16 + (lane >> 2);
#pragma unroll
        for (int nf = 0; nf < 4; nf++) {
            int col = n0 + wn * 32 + nf * 8 + ((lane & 3) << 1);
            float b0 = bias[col], b1 = bias[col + 1];
            float2 v0 = make_float2(acc[mf][nf][0] + b0, acc[mf][nf][1] + b1);
            float2 v1 = make_float2(acc[mf][nf][2] + b0, acc[mf][nf][3] + b1);
            *(float2*)(C + (size_t)row0 * G_N + col) = v0;
            *(float2*)(C + (size_t)(row0 + 8) * G_N + col) = v1;
        }
    }
}

// ---------------------------------------------------------------------------
// Flash attention (fp32, online softmax) — unchanged from passing R3 kernel.
// ---------------------------------------------------------------------------
__global__ __launch_bounds__(256) void flash_attn_kernel(
    const float* __restrict__ Q, const float* __restrict__ K,
    const float* __restrict__ V, const int* __restrict__ mask,
    float* __restrict__ O)
{
    extern __shared__ float sm[];
    float* Qs = sm;
    float* Ks = sm + 64 * 65;
    float* Vs = sm + 2 * 64 * 65;

    const int s0 = blockIdx.x * 64;
    const int h  = blockIdx.y;
    const int b  = blockIdx.z;
    const int tid = threadIdx.x;
    const int ty = tid >> 4;
    const int tx = tid & 15;

    const float* Qb = Q + ((size_t)(b * S_LEN + s0)) * ADIM + h * HEADD;
    const float* Kb = K + ((size_t)b * T_LEN) * ADIM + h * HEADD;
    const float* Vb = V + ((size_t)b * T_LEN) * ADIM + h * HEADD;
    const int* mb = mask + (size_t)b * T_LEN;

#pragma unroll
    for (int i = 0; i < 4; i++) {
        int idx = tid + i * 256;
        int r = idx >> 4, c = (idx & 15) << 2;
        float4 v = *(const float4*)(Qb + (size_t)r * ADIM + c);
        Qs[r * 65 + c + 0] = v.x * 0.125f;
        Qs[r * 65 + c + 1] = v.y * 0.125f;
        Qs[r * 65 + c + 2] = v.z * 0.125f;
        Qs[r * 65 + c + 3] = v.w * 0.125f;
    }

    float m_i[4], l_i[4], acc[4][4];
#pragma unroll
    for (int i = 0; i < 4; i++) {
        m_i[i] = -1e30f;
        l_i[i] = 0.0f;
#pragma unroll
        for (int j = 0; j < 4; j++) acc[i][j] = 0.0f;
    }

    for (int t0 = 0; t0 < T_LEN; t0 += 64) {
#pragma unroll
        for (int i = 0; i < 4; i++) {
            int idx = tid + i * 256;
            int r = idx >> 4, c = (idx & 15) << 2;
            float4 kv = *(const float4*)(Kb + (size_t)(t0 + r) * ADIM + c);
            Ks[r * 65 + c + 0] = kv.x;
            Ks[r * 65 + c + 1] = kv.y;
            Ks[r * 65 + c + 2] = kv.z;
            Ks[r * 65 + c + 3] = kv.w;
            float4 vv = *(const float4*)(Vb + (size_t)(t0 + r) * ADIM + c);
            Vs[r * 65 + c + 0] = vv.x;
            Vs[r * 65 + c + 1] = vv.y;
            Vs[r * 65 + c + 2] = vv.z;
            Vs[r * 65 + c + 3] = vv.w;
        }
        __syncthreads();

        float sc[4][4];
#pragma unroll
        for (int i = 0; i < 4; i++)
#pragma unroll
            for (int j = 0; j < 4; j++) sc[i][j] = 0.0f;

#pragma unroll 8
        for (int d = 0; d < 64; d++) {
            float q[4], kk[4];
#pragma unroll
            for (int i = 0; i < 4; i++) q[i] = Qs[(ty * 4 + i) * 65 + d];
#pragma unroll
            for (int j = 0; j < 4; j++) kk[j] = Ks[(tx * 4 + j) * 65 + d];
#pragma unroll
            for (int i = 0; i < 4; i++)
#pragma unroll
                for (int j = 0; j < 4; j++)
                    sc[i][j] = fmaf(q[i], kk[j], sc[i][j]);
        }

#pragma unroll
        for (int j = 0; j < 4; j++) {
            if (mb[t0 + tx * 4 + j] == 0) {
#pragma unroll
                for (int i = 0; i < 4; i++) sc[i][j] = -100000.0f;
            }
        }

#pragma unroll
        for (int i = 0; i < 4; i++) {
            float mx = fmaxf(fmaxf(sc[i][0], sc[i][1]), fmaxf(sc[i][2], sc[i][3]));
#pragma unroll
            for (int o = 8; o >= 1; o >>= 1)
                mx = fmaxf(mx, __shfl_xor_sync(0xffffffffu, mx, o, 16));
            float mnew = fmaxf(m_i[i], mx);
            float p0 = __expf(sc[i][0] - mnew);
            float p1 = __expf(sc[i][1] - mnew);
            float p2 = __expf(sc[i][2] - mnew);
            float p3 = __expf(sc[i][3] - mnew);
            sc[i][0] = p0; sc[i][1] = p1; sc[i][2] = p2; sc[i][3] = p3;
            float ls = p0 + p1 + p2 + p3;
#pragma unroll
            for (int o = 8; o >= 1; o >>= 1)
                ls += __shfl_xor_sync(0xffffffffu, ls, o, 16);
            float alpha = __expf(m_i[i] - mnew);
            l_i[i] = l_i[i] * alpha + ls;
            m_i[i] = mnew;
#pragma unroll
            for (int j = 0; j < 4; j++) acc[i][j] *= alpha;
        }

        __syncthreads();

#pragma unroll
        for (int i = 0; i < 4; i++)
#pragma unroll
            for (int j = 0; j < 4; j++)
                Ks[(ty * 4 + i) * 65 + tx * 4 + j] = sc[i][j];
        __syncthreads();

#pragma unroll 8
        for (int c = 0; c < 64; c++) {
            float p[4], vv[4];
#pragma unroll
            for (int i = 0; i < 4; i++) p[i] = Ks[(ty * 4 + i) * 65 + c];
#pragma unroll
            for (int j = 0; j < 4; j++) vv[j] = Vs[c * 65 + tx * 4 + j];
#pragma unroll
            for (int i = 0; i < 4; i++)
#pragma unroll
                for (int j = 0; j < 4; j++)
                    acc[i][j] = fmaf(p[i], vv[j], acc[i][j]);
        }
        __syncthreads();
    }

#pragma unroll
    for (int i = 0; i < 4; i++) {
        float inv = 1.0f / l_i[i];
        int row = s0 + ty * 4 + i;
        float4 o;
        o.x = acc[i][0] * inv;
        o.y = acc[i][1] * inv;
        o.z = acc[i][2] * inv;
        o.w = acc[i][3] * inv;
        *(float4*)(O + ((size_t)(b * S_LEN + row)) * ADIM + h * HEADD + tx * 4) = o;
    }
}

// ---------------------------------------------------------------------------
// Launch
// ---------------------------------------------------------------------------
extern "C" void kernel_launch(void* const* d_in, const int* in_sizes, int n_in,
                              void* d_out, int out_size)
{
    const float* x  = (const float*)d_in[0];
    const float* y  = (const float*)d_in[1];
    const int*   mask = (const int*)d_in[2];
    const float* wq = (const float*)d_in[3];
    const float* bq = (const float*)d_in[4];
    const float* wk = (const float*)d_in[5];
    const float* bk = (const float*)d_in[6];
    const float* wv = (const float*)d_in[7];
    const float* bv = (const float*)d_in[8];
    const float* wo = (const float*)d_in[9];
    const float* bo = (const float*)d_in[10];
    float* out = (float*)d_out;

    float *Qp, *Kp, *Vp, *Op;
    cudaGetSymbolAddress((void**)&Qp, g_Q);
    cudaGetSymbolAddress((void**)&Kp, g_K);
    cudaGetSymbolAddress((void**)&Vp, g_V);
    cudaGetSymbolAddress((void**)&Op, g_O);
    __nv_bfloat16 *xh, *xl, *yh, *yl, *oh, *ol;
    __nv_bfloat16 *wqh, *wql, *wkh, *wkl, *wvh, *wvl, *woh, *wol;
    cudaGetSymbolAddress((void**)&xh, g_xh);  cudaGetSymbolAddress((void**)&xl, g_xl);
    cudaGetSymbolAddress((void**)&yh, g_yh);  cudaGetSymbolAddress((void**)&yl, g_yl);
    cudaGetSymbolAddress((void**)&oh, g_oh);  cudaGetSymbolAddress((void**)&ol, g_ol);
    cudaGetSymbolAddress((void**)&wqh, g_wqh); cudaGetSymbolAddress((void**)&wql, g_wql);
    cudaGetSymbolAddress((void**)&wkh, g_wkh); cudaGetSymbolAddress((void**)&wkl, g_wkl);
    cudaGetSymbolAddress((void**)&wvh, g_wvh); cudaGetSymbolAddress((void**)&wvl, g_wvl);
    cudaGetSymbolAddress((void**)&woh, g_woh); cudaGetSymbolAddress((void**)&wol, g_wol);

    const int attn_smem = 3 * 64 * 65 * 4;  // 49920 bytes
    cudaFuncSetAttribute(flash_attn_kernel,
                         cudaFuncAttributeMaxDynamicSharedMemorySize, attn_smem);
    cudaFuncSetAttribute(gemm_mma_kernel,
                         cudaFuncAttributeMaxDynamicSharedMemorySize, GEMM_DSMEM);

    const int n4_act = MROWS * HDIM / 4;

    // Split activations to bf16 hi/lo
    split_kernel<<<(n4_act + 255) / 256, 256>>>((const float4*)x, (uint2*)xh, (uint2*)xl, n4_act);
    split_kernel<<<(n4_act + 255) / 256, 256>>>((const float4*)y, (uint2*)yh, (uint2*)yl, n4_act);

    // Transpose + split weights
    dim3 tg(32, 32), tb(32, 8);
    transpose_split_kernel<<<tg, tb>>>(wq, wqh, wql);
    transpose_split_kernel<<<tg, tb>>>(wk, wkh, wkl);
    transpose_split_kernel<<<tg, tb>>>(wv, wvh, wvl);
    transpose_split_kernel<<<tg, tb>>>(wo, woh, wol);

    // mma.sync projections
    dim3 gg(G_N / 128, MROWS / 128);   // (8, 64)
    gemm_mma_kernel<<<gg, 256, GEMM_DSMEM>>>(xh, xl, wqh, wql, bq, Qp);
    gemm_mma_kernel<<<gg, 256, GEMM_DSMEM>>>(yh, yl, wkh, wkl, bk, Kp);
    gemm_mma_kernel<<<gg, 256, GEMM_DSMEM>>>(yh, yl, wvh, wvl, bv, Vp);

    // Attention (fp32)
    dim3 ga(S_LEN / 64, NHEAD, BB);
    flash_attn_kernel<<<ga, 256, attn_smem>>>(Qp, Kp, Vp, mask, Op);

    // Output projection
    split_kernel<<<(n4_act + 255) / 256, 256>>>((const float4*)Op, (uint2*)oh, (uint2*)ol, n4_act);
    gemm_mma_kernel<<<gg, 256, GEMM_DSMEM>>>(oh, ol, woh, wol, bo, out);
}

// round 6
// speedup vs baseline: 1.7794x; 1.3077x over previous
#include <cuda_runtime.h>
#include <cuda_bf16.h>
#include <cstdint>

// Problem constants
#define BB     4
#define S_LEN  2048
#define T_LEN  2048
#define HDIM   1024
#define ADIM   1024
#define NHEAD  16
#define HEADD  64
#define MROWS  8192   // B*S == B*T

// ---------------------------------------------------------------------------
// Device scratch (no allocations allowed) — all bf16 hi/lo pairs
// ---------------------------------------------------------------------------
__device__ __align__(16) __nv_bfloat16 g_xh[MROWS * HDIM];
__device__ __align__(16) __nv_bfloat16 g_xl[MROWS * HDIM];
__device__ __align__(16) __nv_bfloat16 g_yh[MROWS * HDIM];
__device__ __align__(16) __nv_bfloat16 g_yl[MROWS * HDIM];
__device__ __align__(16) __nv_bfloat16 g_qh[MROWS * ADIM];
__device__ __align__(16) __nv_bfloat16 g_ql[MROWS * ADIM];
__device__ __align__(16) __nv_bfloat16 g_kh[MROWS * ADIM];
__device__ __align__(16) __nv_bfloat16 g_kl[MROWS * ADIM];
__device__ __align__(16) __nv_bfloat16 g_vh[MROWS * ADIM];
__device__ __align__(16) __nv_bfloat16 g_vl[MROWS * ADIM];
__device__ __align__(16) __nv_bfloat16 g_oh[MROWS * ADIM];
__device__ __align__(16) __nv_bfloat16 g_ol[MROWS * ADIM];
// transposed weights hi/lo: Bt[n][k] = W[k][n]
__device__ __align__(16) __nv_bfloat16 g_wqh[ADIM * HDIM];
__device__ __align__(16) __nv_bfloat16 g_wql[ADIM * HDIM];
__device__ __align__(16) __nv_bfloat16 g_wkh[ADIM * HDIM];
__device__ __align__(16) __nv_bfloat16 g_wkl[ADIM * HDIM];
__device__ __align__(16) __nv_bfloat16 g_wvh[ADIM * HDIM];
__device__ __align__(16) __nv_bfloat16 g_wvl[ADIM * HDIM];
__device__ __align__(16) __nv_bfloat16 g_woh[HDIM * ADIM];
__device__ __align__(16) __nv_bfloat16 g_wol[HDIM * ADIM];

// ---------------------------------------------------------------------------
// PTX helpers (sm_80-era: legal on plain sm_103 target)
// ---------------------------------------------------------------------------
__device__ __forceinline__ uint32_t smem_u32(const void* p) {
    uint32_t a;
    asm("{ .reg .u64 t; cvta.to.shared.u64 t, %1; cvt.u32.u64 %0, t; }" : "=r"(a) : "l"(p));
    return a;
}

#define CP_ASYNC16(smem, gptr) \
    asm volatile("cp.async.cg.shared.global [%0], [%1], 16;" \
                 :: "r"((uint32_t)(smem)), "l"(gptr) : "memory")
#define CP_ASYNC_COMMIT() asm volatile("cp.async.commit_group;" ::: "memory")
#define CP_ASYNC_WAIT0()  asm volatile("cp.async.wait_group 0;" ::: "memory")
#define CP_ASYNC_WAIT1()  asm volatile("cp.async.wait_group 1;" ::: "memory")

#define LDSM_X4(r0, r1, r2, r3, a) \
    asm volatile("ldmatrix.sync.aligned.m8n8.x4.shared.b16 {%0,%1,%2,%3}, [%4];" \
                 : "=r"(r0), "=r"(r1), "=r"(r2), "=r"(r3) : "r"(a))
#define LDSM_X4_T(r0, r1, r2, r3, a) \
    asm volatile("ldmatrix.sync.aligned.m8n8.x4.trans.shared.b16 {%0,%1,%2,%3}, [%4];" \
                 : "=r"(r0), "=r"(r1), "=r"(r2), "=r"(r3) : "r"(a))
#define LDSM_X2(r0, r1, a) \
    asm volatile("ldmatrix.sync.aligned.m8n8.x2.shared.b16 {%0,%1}, [%2];" \
                 : "=r"(r0), "=r"(r1) : "r"(a))

#define MMA_BF16(d, a, b) \
    asm volatile("mma.sync.aligned.m16n8k16.row.col.f32.bf16.bf16.f32 " \
                 "{%0,%1,%2,%3}, {%4,%5,%6,%7}, {%8,%9}, {%0,%1,%2,%3};" \
                 : "+f"((d)[0]), "+f"((d)[1]), "+f"((d)[2]), "+f"((d)[3]) \
                 : "r"((a)[0]), "r"((a)[1]), "r"((a)[2]), "r"((a)[3]), \
                   "r"((b)[0]), "r"((b)[1]))

// ---------------------------------------------------------------------------
// Split fp32 -> bf16 hi/lo
// ---------------------------------------------------------------------------
__global__ __launch_bounds__(256) void split_kernel(
    const float4* __restrict__ in, uint2* __restrict__ hi, uint2* __restrict__ lo, int n4)
{
    int i = blockIdx.x * 256 + threadIdx.x;
    if (i >= n4) return;
    float4 v = in[i];
    __nv_bfloat16 h0 = __float2bfloat16(v.x), h1 = __float2bfloat16(v.y);
    __nv_bfloat16 h2 = __float2bfloat16(v.z), h3 = __float2bfloat16(v.w);
    __nv_bfloat16 l0 = __float2bfloat16(v.x - __bfloat162float(h0));
    __nv_bfloat16 l1 = __float2bfloat16(v.y - __bfloat162float(h1));
    __nv_bfloat16 l2 = __float2bfloat16(v.z - __bfloat162float(h2));
    __nv_bfloat16 l3 = __float2bfloat16(v.w - __bfloat162float(h3));
    uint2 hw, lw;
    hw.x = (uint32_t)__bfloat16_as_ushort(h0) | ((uint32_t)__bfloat16_as_ushort(h1) << 16);
    hw.y = (uint32_t)__bfloat16_as_ushort(h2) | ((uint32_t)__bfloat16_as_ushort(h3) << 16);
    lw.x = (uint32_t)__bfloat16_as_ushort(l0) | ((uint32_t)__bfloat16_as_ushort(l1) << 16);
    lw.y = (uint32_t)__bfloat16_as_ushort(l2) | ((uint32_t)__bfloat16_as_ushort(l3) << 16);
    hi[i] = hw;
    lo[i] = lw;
}

// ---------------------------------------------------------------------------
// Transpose + split weights
// ---------------------------------------------------------------------------
__global__ __launch_bounds__(256) void transpose_split_kernel(
    const float* __restrict__ W, __nv_bfloat16* __restrict__ th, __nv_bfloat16* __restrict__ tl)
{
    __shared__ float t[32][33];
    int tx = threadIdx.x, ty = threadIdx.y;
    int n0 = blockIdx.x * 32, k0 = blockIdx.y * 32;
#pragma unroll
    for (int i = 0; i < 32; i += 8)
        t[ty + i][tx] = W[(size_t)(k0 + ty + i) * 1024 + n0 + tx];
    __syncthreads();
#pragma unroll
    for (int i = 0; i < 32; i += 8) {
        float v = t[tx][ty + i];
        __nv_bfloat16 h = __float2bfloat16(v);
        __nv_bfloat16 l = __float2bfloat16(v - __bfloat162float(h));
        size_t o = (size_t)(n0 + ty + i) * 1024 + k0 + tx;
        th[o] = h;
        tl[o] = l;
    }
}

// ---------------------------------------------------------------------------
// mma.sync split-bf16 GEMM (template epilogue):
//   OUTF32=1: C = acc + bias (fp32)
//   OUTF32=0: out = scale*(acc+bias) -> bf16 hi/lo pair
// ---------------------------------------------------------------------------
#define G_K     1024
#define G_N     1024
#define BKC     32
#define PAD_B   80
#define MAT_B   (128 * PAD_B)
#define OFF_AH  0
#define OFF_AL  (1 * MAT_B)
#define OFF_BH  (2 * MAT_B)
#define OFF_BL  (3 * MAT_B)
#define STAGE_B (4 * MAT_B)
#define GEMM_DSMEM (2 * STAGE_B)

__device__ __forceinline__ void gemm_load_stage(
    uint32_t sb, const __nv_bfloat16* __restrict__ Ah, const __nv_bfloat16* __restrict__ Al,
    const __nv_bfloat16* __restrict__ Bh, const __nv_bfloat16* __restrict__ Bl,
    int m0, int n0, int k0, int tid)
{
#pragma unroll
    for (int i = 0; i < 2; i++) {
        int idx = tid + i * 256;
        int r = idx >> 2, sg = idx & 3;
        uint32_t so = (uint32_t)(r * PAD_B + sg * 16);
        size_t ga = (size_t)(m0 + r) * G_K + k0 + sg * 8;
        size_t gb = (size_t)(n0 + r) * G_K + k0 + sg * 8;
        CP_ASYNC16(sb + OFF_AH + so, Ah + ga);
        CP_ASYNC16(sb + OFF_AL + so, Al + ga);
        CP_ASYNC16(sb + OFF_BH + so, Bh + gb);
        CP_ASYNC16(sb + OFF_BL + so, Bl + gb);
    }
}

template <int OUTF32>
__global__ __launch_bounds__(256) void gemm_mma_kernel(
    const __nv_bfloat16* __restrict__ Ah, const __nv_bfloat16* __restrict__ Al,
    const __nv_bfloat16* __restrict__ Bh, const __nv_bfloat16* __restrict__ Bl,
    const float* __restrict__ bias, float* __restrict__ Cf,
    __nv_bfloat16* __restrict__ Ch, __nv_bfloat16* __restrict__ Cl, float scale)
{
    extern __shared__ __align__(16) char dsm[];
    const uint32_t sm0 = smem_u32(dsm);
    const int tid = threadIdx.x;
    const int wid = tid >> 5;
    const int lane = tid & 31;
    const int wm = wid >> 2;
    const int wn = wid & 3;
    const int m0 = blockIdx.y * 128;
    const int n0 = blockIdx.x * 128;

    float acc[4][4][4];
#pragma unroll
    for (int i = 0; i < 4; i++)
#pragma unroll
        for (int j = 0; j < 4; j++)
#pragma unroll
            for (int c = 0; c < 4; c++) acc[i][j][c] = 0.0f;

    const int t4 = lane >> 3;
    const uint32_t a_lane_off = (uint32_t)(((lane & 7) + ((t4 & 1) << 3)) * PAD_B
                                           + ((t4 >> 1) << 3) * 2);
    const int li = lane & 15;
    const uint32_t b_lane_off = (uint32_t)((li & 7) * PAD_B + ((li >> 3) << 3) * 2);

    gemm_load_stage(sm0, Ah, Al, Bh, Bl, m0, n0, 0, tid);
    CP_ASYNC_COMMIT();

    const int NCH = G_K / BKC;
    for (int kc = 0; kc < NCH; kc++) {
        const uint32_t sb = sm0 + (kc & 1) * STAGE_B;
        if (kc + 1 < NCH) {
            gemm_load_stage(sm0 + ((kc + 1) & 1) * STAGE_B, Ah, Al, Bh, Bl,
                            m0, n0, (kc + 1) * BKC, tid);
            CP_ASYNC_COMMIT();
            CP_ASYNC_WAIT1();
        } else {
            CP_ASYNC_WAIT0();
        }
        __syncthreads();

#pragma unroll
        for (int ks = 0; ks < 2; ks++) {
            const uint32_t kb = (uint32_t)(ks * 16 * 2);
            uint32_t bh[4][2], bl[4][2];
#pragma unroll
            for (int nf = 0; nf < 4; nf++) {
                uint32_t base = (uint32_t)((wn * 32 + nf * 8) * PAD_B) + kb + b_lane_off;
                LDSM_X2(bh[nf][0], bh[nf][1], sb + OFF_BH + base);
                LDSM_X2(bl[nf][0], bl[nf][1], sb + OFF_BL + base);
            }
#pragma unroll
            for (int mf = 0; mf < 4; mf++) {
                uint32_t base = (uint32_t)((wm * 64 + mf * 16) * PAD_B) + kb + a_lane_off;
                uint32_t ah[4], al[4];
                LDSM_X4(ah[0], ah[1], ah[2], ah[3], sb + OFF_AH + base);
                LDSM_X4(al[0], al[1], al[2], al[3], sb + OFF_AL + base);
#pragma unroll
                for (int nf = 0; nf < 4; nf++) {
                    MMA_BF16(acc[mf][nf], ah, bh[nf]);
                    MMA_BF16(acc[mf][nf], ah, bl[nf]);
                    MMA_BF16(acc[mf][nf], al, bh[nf]);
                }
            }
        }
        __syncthreads();
    }

#pragma unroll
    for (int mf = 0; mf < 4; mf++) {
        int row0 = m0 + wm * 64 + mf * 16 + (lane >> 2);
#pragma unroll
        for (int nf = 0; nf < 4; nf++) {
            int col = n0 + wn * 32 + nf * 8 + ((lane & 3) << 1);
            float b0 = bias[col], b1 = bias[col + 1];
            if (OUTF32) {
                float2 v0 = make_float2(acc[mf][nf][0] + b0, acc[mf][nf][1] + b1);
                float2 v1 = make_float2(acc[mf][nf][2] + b0, acc[mf][nf][3] + b1);
                *(float2*)(Cf + (size_t)row0 * G_N + col) = v0;
                *(float2*)(Cf + (size_t)(row0 + 8) * G_N + col) = v1;
            } else {
                float o0 = scale * (acc[mf][nf][0] + b0);
                float o1 = scale * (acc[mf][nf][1] + b1);
                float o2 = scale * (acc[mf][nf][2] + b0);
                float o3 = scale * (acc[mf][nf][3] + b1);
                __nv_bfloat162 h0 = __float22bfloat162_rn(make_float2(o0, o1));
                float2 hf0 = __bfloat1622float2(h0);
                __nv_bfloat162 l0 = __float22bfloat162_rn(make_float2(o0 - hf0.x, o1 - hf0.y));
                __nv_bfloat162 h1 = __float22bfloat162_rn(make_float2(o2, o3));
                float2 hf1 = __bfloat1622float2(h1);
                __nv_bfloat162 l1 = __float22bfloat162_rn(make_float2(o2 - hf1.x, o3 - hf1.y));
                *(__nv_bfloat162*)(Ch + (size_t)row0 * G_N + col) = h0;
                *(__nv_bfloat162*)(Cl + (size_t)row0 * G_N + col) = l0;
                *(__nv_bfloat162*)(Ch + (size_t)(row0 + 8) * G_N + col) = h1;
                *(__nv_bfloat162*)(Cl + (size_t)(row0 + 8) * G_N + col) = l1;
            }
        }
    }
}

// ---------------------------------------------------------------------------
// Tensorized flash attention (split-bf16 mma.sync, online softmax).
// Grid (S/128, NH, B), 256 threads / 8 warps; warp owns 16 q-rows.
// Smem: 2 stages of [Kh|Kl|Vh|Vl], each 64 rows x 72 bf16 (144B padded).
// Q hi/lo fragments preloaded (staged through stage-0 buffer).
// ---------------------------------------------------------------------------
#define AT_PADE 72                      // elems per padded row
#define AT_ROWB 144                     // bytes per row
#define AT_MATB (64 * AT_ROWB)          // 9216 bytes per matrix
#define AT_STGB (4 * AT_MATB)           // 36864 per stage
#define AT_DSMEM (2 * AT_STGB)          // 73728

__device__ __forceinline__ void at_load_kv(
    uint32_t sb, const __nv_bfloat16* khb, const __nv_bfloat16* klb,
    const __nv_bfloat16* vhb, const __nv_bfloat16* vlb, int t0, int tid)
{
#pragma unroll
    for (int it = 0; it < 2; it++) {
        int id = tid + it * 256;
        int r = id >> 3, c = id & 7;
        uint32_t so = (uint32_t)(r * AT_ROWB + c * 16);
        size_t go = (size_t)(t0 + r) * ADIM + c * 8;
        CP_ASYNC16(sb + 0 * AT_MATB + so, khb + go);
        CP_ASYNC16(sb + 1 * AT_MATB + so, klb + go);
        CP_ASYNC16(sb + 2 * AT_MATB + so, vhb + go);
        CP_ASYNC16(sb + 3 * AT_MATB + so, vlb + go);
    }
}

__global__ __launch_bounds__(256) void flash_mma_kernel(
    const __nv_bfloat16* __restrict__ qh, const __nv_bfloat16* __restrict__ ql,
    const __nv_bfloat16* __restrict__ kh, const __nv_bfloat16* __restrict__ kl,
    const __nv_bfloat16* __restrict__ vh, const __nv_bfloat16* __restrict__ vl,
    const int* __restrict__ mask,
    __nv_bfloat16* __restrict__ oh, __nv_bfloat16* __restrict__ ol)
{
    extern __shared__ __align__(16) char dsm[];
    const uint32_t sm0 = smem_u32(dsm);
    const int tid = threadIdx.x;
    const int w = tid >> 5;
    const int lane = tid & 31;
    const int s0 = blockIdx.x * 128;
    const int h = blockIdx.y;
    const int b = blockIdx.z;

    const __nv_bfloat16* qhb = qh + (size_t)(b * S_LEN + s0) * ADIM + h * HEADD;
    const __nv_bfloat16* qlb = ql + (size_t)(b * S_LEN + s0) * ADIM + h * HEADD;
    const __nv_bfloat16* khb = kh + (size_t)(b * T_LEN) * ADIM + h * HEADD;
    const __nv_bfloat16* klb = kl + (size_t)(b * T_LEN) * ADIM + h * HEADD;
    const __nv_bfloat16* vhb = vh + (size_t)(b * T_LEN) * ADIM + h * HEADD;
    const __nv_bfloat16* vlb = vl + (size_t)(b * T_LEN) * ADIM + h * HEADD;
    const int* mb = mask + (size_t)b * T_LEN;

    // --- Stage Q tile (128x64 hi + lo) through stage-0 buffer ---
#pragma unroll
    for (int it = 0; it < 4; it++) {
        int id = tid + it * 256;
        int r = id >> 3, c = id & 7;
        uint32_t so = (uint32_t)(r * AT_ROWB + c * 16);
        size_t go = (size_t)r * ADIM + c * 8;
        CP_ASYNC16(sm0 + so, qhb + go);
        CP_ASYNC16(sm0 + 128 * AT_ROWB + so, qlb + go);
    }
    CP_ASYNC_COMMIT();
    CP_ASYNC_WAIT0();
    __syncthreads();

    // Q fragments: qf[kf][0..3], hi and lo
    const int r8 = lane & 7;
    const int g = lane >> 3;
    uint32_t qfh[4][4], qfl[4][4];
#pragma unroll
    for (int kf = 0; kf < 4; kf++) {
        uint32_t addr = sm0 + (uint32_t)((w * 16 + r8 + (g & 1) * 8) * AT_ROWB
                                         + (16 * kf + (g >> 1) * 8) * 2);
        LDSM_X4(qfh[kf][0], qfh[kf][1], qfh[kf][2], qfh[kf][3], addr);
        LDSM_X4(qfl[kf][0], qfl[kf][1], qfl[kf][2], qfl[kf][3], addr + 128 * AT_ROWB);
    }
    __syncthreads();   // done with stage-0 buffer; reuse for K/V

    float oacc[8][4];
#pragma unroll
    for (int i = 0; i < 8; i++)
#pragma unroll
        for (int c = 0; c < 4; c++) oacc[i][c] = 0.0f;
    float mr0 = -1e30f, mr1 = -1e30f, lr0 = 0.0f, lr1 = 0.0f;

    at_load_kv(sm0, khb, klb, vhb, vlb, 0, tid);
    CP_ASYNC_COMMIT();

    const int c2 = (lane & 3) << 1;
    const int NT = T_LEN / 64;   // 32

    for (int tc = 0; tc < NT; tc++) {
        const uint32_t sb = sm0 + (tc & 1) * AT_STGB;
        if (tc + 1 < NT) {
            at_load_kv(sm0 + ((tc + 1) & 1) * AT_STGB, khb, klb, vhb, vlb, (tc + 1) * 64, tid);
            CP_ASYNC_COMMIT();
            CP_ASYNC_WAIT1();
        } else {
            CP_ASYNC_WAIT0();
        }
        __syncthreads();

        // ---- S = Q K^T (split: qh*kh + qh*kl + ql*kh) ----
        float s[8][4];
#pragma unroll
        for (int i = 0; i < 8; i++)
#pragma unroll
            for (int c = 0; c < 4; c++) s[i][c] = 0.0f;

#pragma unroll
        for (int kf = 0; kf < 4; kf++) {
#pragma unroll
            for (int nfp = 0; nfp < 4; nfp++) {
                uint32_t addrK = sb + (uint32_t)((16 * nfp + r8 + (g & 1) * 8) * AT_ROWB
                                                 + (16 * kf + (g >> 1) * 8) * 2);
                uint32_t r0, r1, r2, r3, u0, u1, u2, u3;
                LDSM_X4(r0, r1, r2, r3, addrK);
                LDSM_X4(u0, u1, u2, u3, addrK + AT_MATB);
                uint32_t bh0[2] = {r0, r2}, bh1[2] = {r1, r3};
                uint32_t bl0[2] = {u0, u2}, bl1[2] = {u1, u3};
                MMA_BF16(s[2 * nfp],     qfh[kf], bh0);
                MMA_BF16(s[2 * nfp],     qfh[kf], bl0);
                MMA_BF16(s[2 * nfp],     qfl[kf], bh0);
                MMA_BF16(s[2 * nfp + 1], qfh[kf], bh1);
                MMA_BF16(s[2 * nfp + 1], qfh[kf], bl1);
                MMA_BF16(s[2 * nfp + 1], qfl[kf], bh1);
            }
        }

        // ---- mask + online softmax (rows lane/4 and lane/4+8 of warp tile) ----
        float mx0 = -1e30f, mx1 = -1e30f;
#pragma unroll
        for (int nf = 0; nf < 8; nf++) {
            int tcol = tc * 64 + nf * 8 + c2;
            int2 mm = *(const int2*)(mb + tcol);
            if (mm.x == 0) { s[nf][0] = -100000.0f; s[nf][2] = -100000.0f; }
            if (mm.y == 0) { s[nf][1] = -100000.0f; s[nf][3] = -100000.0f; }
            mx0 = fmaxf(mx0, fmaxf(s[nf][0], s[nf][1]));
            mx1 = fmaxf(mx1, fmaxf(s[nf][2], s[nf][3]));
        }
        mx0 = fmaxf(mx0, __shfl_xor_sync(0xffffffffu, mx0, 1));
        mx0 = fmaxf(mx0, __shfl_xor_sync(0xffffffffu, mx0, 2));
        mx1 = fmaxf(mx1, __shfl_xor_sync(0xffffffffu, mx1, 1));
        mx1 = fmaxf(mx1, __shfl_xor_sync(0xffffffffu, mx1, 2));

        float mn0 = fmaxf(mr0, mx0), mn1 = fmaxf(mr1, mx1);
        float al0 = __expf(mr0 - mn0), al1 = __expf(mr1 - mn1);
        float sum0 = 0.0f, sum1 = 0.0f;
#pragma unroll
        for (int nf = 0; nf < 8; nf++) {
            s[nf][0] = __expf(s[nf][0] - mn0);
            s[nf][1] = __expf(s[nf][1] - mn0);
            s[nf][2] = __expf(s[nf][2] - mn1);
            s[nf][3] = __expf(s[nf][3] - mn1);
            sum0 += s[nf][0] + s[nf][1];
            sum1 += s[nf][2] + s[nf][3];
        }
        sum0 += __shfl_xor_sync(0xffffffffu, sum0, 1);
        sum0 += __shfl_xor_sync(0xffffffffu, sum0, 2);
        sum1 += __shfl_xor_sync(0xffffffffu, sum1, 1);
        sum1 += __shfl_xor_sync(0xffffffffu, sum1, 2);
        lr0 = lr0 * al0 + sum0;
        lr1 = lr1 * al1 + sum1;
        mr0 = mn0;
        mr1 = mn1;
#pragma unroll
        for (int nf = 0; nf < 8; nf++) {
            oacc[nf][0] *= al0;
            oacc[nf][1] *= al0;
            oacc[nf][2] *= al1;
            oacc[nf][3] *= al1;
        }

        // ---- O += P V (split: ph*vh + ph*vl + pl*vh) ----
#pragma unroll
        for (int kf = 0; kf < 4; kf++) {
            // Build P A-fragments for k-span 16kf..16kf+15 from s[2kf], s[2kf+1]
            uint32_t pah[4], pal[4];
#pragma unroll
            for (int q = 0; q < 2; q++) {
                const float* sp = s[2 * kf + q];
                __nv_bfloat162 h0 = __float22bfloat162_rn(make_float2(sp[0], sp[1]));
                float2 hf0 = __bfloat1622float2(h0);
                __nv_bfloat162 e0 = __float22bfloat162_rn(make_float2(sp[0] - hf0.x, sp[1] - hf0.y));
                __nv_bfloat162 h1 = __float22bfloat162_rn(make_float2(sp[2], sp[3]));
                float2 hf1 = __bfloat1622float2(h1);
                __nv_bfloat162 e1 = __float22bfloat162_rn(make_float2(sp[2] - hf1.x, sp[3] - hf1.y));
                pah[2 * q]     = *(uint32_t*)&h0;
                pah[2 * q + 1] = *(uint32_t*)&h1;
                pal[2 * q]     = *(uint32_t*)&e0;
                pal[2 * q + 1] = *(uint32_t*)&e1;
            }
#pragma unroll
            for (int nfp = 0; nfp < 4; nfp++) {
                uint32_t addrV = sb + 2 * AT_MATB
                               + (uint32_t)((16 * kf + r8 + (g & 1) * 8) * AT_ROWB
                                            + (16 * nfp + (g >> 1) * 8) * 2);
                uint32_t r0, r1, r2, r3, u0, u1, u2, u3;
                LDSM_X4_T(r0, r1, r2, r3, addrV);
                LDSM_X4_T(u0, u1, u2, u3, addrV + AT_MATB);
                uint32_t bvh0[2] = {r0, r1}, bvh1[2] = {r2, r3};
                uint32_t bvl0[2] = {u0, u1}, bvl1[2] = {u2, u3};
                MMA_BF16(oacc[2 * nfp],     pah, bvh0);
                MMA_BF16(oacc[2 * nfp],     pah, bvl0);
                MMA_BF16(oacc[2 * nfp],     pal, bvh0);
                MMA_BF16(oacc[2 * nfp + 1], pah, bvh1);
                MMA_BF16(oacc[2 * nfp + 1], pah, bvl1);
                MMA_BF16(oacc[2 * nfp + 1], pal, bvh1);
            }
        }
        __syncthreads();   // all reads of sb done before it is refilled next iter
    }

    // ---- Normalize + write oh/ol ----
    float inv0 = 1.0f / lr0, inv1 = 1.0f / lr1;
    size_t row0 = (size_t)(b * S_LEN + s0 + w * 16 + (lane >> 2));
    size_t row1 = row0 + 8;
#pragma unroll
    for (int nf = 0; nf < 8; nf++) {
        int col = h * HEADD + nf * 8 + c2;
        float o0 = oacc[nf][0] * inv0, o1 = oacc[nf][1] * inv0;
        float o2 = oacc[nf][2] * inv1, o3 = oacc[nf][3] * inv1;
        __nv_bfloat162 h0 = __float22bfloat162_rn(make_float2(o0, o1));
        float2 hf0 = __bfloat1622float2(h0);
        __nv_bfloat162 e0 = __float22bfloat162_rn(make_float2(o0 - hf0.x, o1 - hf0.y));
        __nv_bfloat162 h1 = __float22bfloat162_rn(make_float2(o2, o3));
        float2 hf1 = __bfloat1622float2(h1);
        __nv_bfloat162 e1 = __float22bfloat162_rn(make_float2(o2 - hf1.x, o3 - hf1.y));
        *(__nv_bfloat162*)(oh + row0 * ADIM + col) = h0;
        *(__nv_bfloat162*)(ol + row0 * ADIM + col) = e0;
        *(__nv_bfloat162*)(oh + row1 * ADIM + col) = h1;
        *(__nv_bfloat162*)(ol + row1 * ADIM + col) = e1;
    }
}

// ---------------------------------------------------------------------------
// Launch
// ---------------------------------------------------------------------------
extern "C" void kernel_launch(void* const* d_in, const int* in_sizes, int n_in,
                              void* d_out, int out_size)
{
    const float* x  = (const float*)d_in[0];
    const float* y  = (const float*)d_in[1];
    const int*   mask = (const int*)d_in[2];
    const float* wq = (const float*)d_in[3];
    const float* bq = (const float*)d_in[4];
    const float* wk = (const float*)d_in[5];
    const float* bk = (const float*)d_in[6];
    const float* wv = (const float*)d_in[7];
    const float* bv = (const float*)d_in[8];
    const float* wo = (const float*)d_in[9];
    const float* bo = (const float*)d_in[10];
    float* out = (float*)d_out;

    __nv_bfloat16 *xh, *xl, *yh, *yl, *qhp, *qlp, *khp, *klp, *vhp, *vlp, *ohp, *olp;
    __nv_bfloat16 *wqh, *wql, *wkh, *wkl, *wvh, *wvl, *woh, *wol;
    cudaGetSymbolAddress((void**)&xh, g_xh);   cudaGetSymbolAddress((void**)&xl, g_xl);
    cudaGetSymbolAddress((void**)&yh, g_yh);   cudaGetSymbolAddress((void**)&yl, g_yl);
    cudaGetSymbolAddress((void**)&qhp, g_qh);  cudaGetSymbolAddress((void**)&qlp, g_ql);
    cudaGetSymbolAddress((void**)&khp, g_kh);  cudaGetSymbolAddress((void**)&klp, g_kl);
    cudaGetSymbolAddress((void**)&vhp, g_vh);  cudaGetSymbolAddress((void**)&vlp, g_vl);
    cudaGetSymbolAddress((void**)&ohp, g_oh);  cudaGetSymbolAddress((void**)&olp, g_ol);
    cudaGetSymbolAddress((void**)&wqh, g_wqh); cudaGetSymbolAddress((void**)&wql, g_wql);
    cudaGetSymbolAddress((void**)&wkh, g_wkh); cudaGetSymbolAddress((void**)&wkl, g_wkl);
    cudaGetSymbolAddress((void**)&wvh, g_wvh); cudaGetSymbolAddress((void**)&wvl, g_wvl);
    cudaGetSymbolAddress((void**)&woh, g_woh); cudaGetSymbolAddress((void**)&wol, g_wol);

    cudaFuncSetAttribute(gemm_mma_kernel<0>,
                         cudaFuncAttributeMaxDynamicSharedMemorySize, GEMM_DSMEM);
    cudaFuncSetAttribute(gemm_mma_kernel<1>,
                         cudaFuncAttributeMaxDynamicSharedMemorySize, GEMM_DSMEM);
    cudaFuncSetAttribute(flash_mma_kernel,
                         cudaFuncAttributeMaxDynamicSharedMemorySize, AT_DSMEM);

    const int n4_act = MROWS * HDIM / 4;

    // Split activations
    split_kernel<<<(n4_act + 255) / 256, 256>>>((const float4*)x, (uint2*)xh, (uint2*)xl, n4_act);
    split_kernel<<<(n4_act + 255) / 256, 256>>>((const float4*)y, (uint2*)yh, (uint2*)yl, n4_act);

    // Transpose + split weights
    dim3 tg(32, 32), tb(32, 8);
    transpose_split_kernel<<<tg, tb>>>(wq, wqh, wql);
    transpose_split_kernel<<<tg, tb>>>(wk, wkh, wkl);
    transpose_split_kernel<<<tg, tb>>>(wv, wvh, wvl);
    transpose_split_kernel<<<tg, tb>>>(wo, woh, wol);

    // QKV projections -> bf16 hi/lo (Q pre-scaled by 1/sqrt(64))
    dim3 gg(G_N / 128, MROWS / 128);
    gemm_mma_kernel<0><<<gg, 256, GEMM_DSMEM>>>(xh, xl, wqh, wql, bq, nullptr, qhp, qlp, 0.125f);
    gemm_mma_kernel<0><<<gg, 256, GEMM_DSMEM>>>(yh, yl, wkh, wkl, bk, nullptr, khp, klp, 1.0f);
    gemm_mma_kernel<0><<<gg, 256, GEMM_DSMEM>>>(yh, yl, wvh, wvl, bv, nullptr, vhp, vlp, 1.0f);

    // Tensorized flash attention -> oh/ol
    dim3 ga(S_LEN / 128, NHEAD, BB);
    flash_mma_kernel<<<ga, 256, AT_DSMEM>>>(qhp, qlp, khp, klp, vhp, vlp, mask, ohp, olp);

    // Output projection -> fp32 out
    gemm_mma_kernel<1><<<gg, 256, GEMM_DSMEM>>>(ohp, olp, woh, wol, bo, out, nullptr, nullptr, 1.0f);
}

// round 7
// speedup vs baseline: 2.9600x; 1.6635x over previous
#include <cuda_runtime.h>
#include <cuda_bf16.h>
#include <cstdint>

// Problem constants
#define BB     4
#define S_LEN  2048
#define T_LEN  2048
#define HDIM   1024
#define ADIM   1024
#define NHEAD  16
#define HEADD  64
#define MROWS  8192   // B*S == B*T

// ---------------------------------------------------------------------------
// Device scratch (no allocations allowed) — all bf16 hi/lo pairs
// ---------------------------------------------------------------------------
__device__ __align__(16) __nv_bfloat16 g_xh[MROWS * HDIM];
__device__ __align__(16) __nv_bfloat16 g_xl[MROWS * HDIM];
__device__ __align__(16) __nv_bfloat16 g_yh[MROWS * HDIM];
__device__ __align__(16) __nv_bfloat16 g_yl[MROWS * HDIM];
__device__ __align__(16) __nv_bfloat16 g_qh[MROWS * ADIM];
__device__ __align__(16) __nv_bfloat16 g_ql[MROWS * ADIM];
__device__ __align__(16) __nv_bfloat16 g_kh[MROWS * ADIM];
__device__ __align__(16) __nv_bfloat16 g_kl[MROWS * ADIM];
__device__ __align__(16) __nv_bfloat16 g_vh[MROWS * ADIM];
__device__ __align__(16) __nv_bfloat16 g_vl[MROWS * ADIM];
__device__ __align__(16) __nv_bfloat16 g_oh[MROWS * ADIM];
__device__ __align__(16) __nv_bfloat16 g_ol[MROWS * ADIM];
// transposed weights hi/lo: Bt[n][k] = W[k][n]
__device__ __align__(16) __nv_bfloat16 g_wqh[ADIM * HDIM];
__device__ __align__(16) __nv_bfloat16 g_wql[ADIM * HDIM];
__device__ __align__(16) __nv_bfloat16 g_wkh[ADIM * HDIM];
__device__ __align__(16) __nv_bfloat16 g_wkl[ADIM * HDIM];
__device__ __align__(16) __nv_bfloat16 g_wvh[ADIM * HDIM];
__device__ __align__(16) __nv_bfloat16 g_wvl[ADIM * HDIM];
__device__ __align__(16) __nv_bfloat16 g_woh[HDIM * ADIM];
__device__ __align__(16) __nv_bfloat16 g_wol[HDIM * ADIM];

// ---------------------------------------------------------------------------
// PTX helpers (sm_80-era: legal on plain sm_103 target)
// ---------------------------------------------------------------------------
__device__ __forceinline__ uint32_t smem_u32(const void* p) {
    uint32_t a;
    asm("{ .reg .u64 t; cvta.to.shared.u64 t, %1; cvt.u32.u64 %0, t; }" : "=r"(a) : "l"(p));
    return a;
}

#define CP_ASYNC16(smem, gptr) \
    asm volatile("cp.async.cg.shared.global [%0], [%1], 16;" \
                 :: "r"((uint32_t)(smem)), "l"(gptr) : "memory")
#define CP_ASYNC_COMMIT() asm volatile("cp.async.commit_group;" ::: "memory")
#define CP_ASYNC_WAIT0()  asm volatile("cp.async.wait_group 0;" ::: "memory")
#define CP_ASYNC_WAIT1()  asm volatile("cp.async.wait_group 1;" ::: "memory")

#define LDSM_X4(r0, r1, r2, r3, a) \
    asm volatile("ldmatrix.sync.aligned.m8n8.x4.shared.b16 {%0,%1,%2,%3}, [%4];" \
                 : "=r"(r0), "=r"(r1), "=r"(r2), "=r"(r3) : "r"(a))
#define LDSM_X4_T(r0, r1, r2, r3, a) \
    asm volatile("ldmatrix.sync.aligned.m8n8.x4.trans.shared.b16 {%0,%1,%2,%3}, [%4];" \
                 : "=r"(r0), "=r"(r1), "=r"(r2), "=r"(r3) : "r"(a))
#define LDSM_X2(r0, r1, a) \
    asm volatile("ldmatrix.sync.aligned.m8n8.x2.shared.b16 {%0,%1}, [%2];" \
                 : "=r"(r0), "=r"(r1) : "r"(a))

#define MMA_BF16(d, a, b) \
    asm volatile("mma.sync.aligned.m16n8k16.row.col.f32.bf16.bf16.f32 " \
                 "{%0,%1,%2,%3}, {%4,%5,%6,%7}, {%8,%9}, {%0,%1,%2,%3};" \
                 : "+f"((d)[0]), "+f"((d)[1]), "+f"((d)[2]), "+f"((d)[3]) \
                 : "r"((a)[0]), "r"((a)[1]), "r"((a)[2]), "r"((a)[3]), \
                   "r"((b)[0]), "r"((b)[1]))

// ---------------------------------------------------------------------------
// Split fp32 -> bf16 hi/lo
// ---------------------------------------------------------------------------
__global__ __launch_bounds__(256) void split_kernel(
    const float4* __restrict__ in, uint2* __restrict__ hi, uint2* __restrict__ lo, int n4)
{
    int i = blockIdx.x * 256 + threadIdx.x;
    if (i >= n4) return;
    float4 v = in[i];
    __nv_bfloat16 h0 = __float2bfloat16(v.x), h1 = __float2bfloat16(v.y);
    __nv_bfloat16 h2 = __float2bfloat16(v.z), h3 = __float2bfloat16(v.w);
    __nv_bfloat16 l0 = __float2bfloat16(v.x - __bfloat162float(h0));
    __nv_bfloat16 l1 = __float2bfloat16(v.y - __bfloat162float(h1));
    __nv_bfloat16 l2 = __float2bfloat16(v.z - __bfloat162float(h2));
    __nv_bfloat16 l3 = __float2bfloat16(v.w - __bfloat162float(h3));
    uint2 hw, lw;
    hw.x = (uint32_t)__bfloat16_as_ushort(h0) | ((uint32_t)__bfloat16_as_ushort(h1) << 16);
    hw.y = (uint32_t)__bfloat16_as_ushort(h2) | ((uint32_t)__bfloat16_as_ushort(h3) << 16);
    lw.x = (uint32_t)__bfloat16_as_ushort(l0) | ((uint32_t)__bfloat16_as_ushort(l1) << 16);
    lw.y = (uint32_t)__bfloat16_as_ushort(l2) | ((uint32_t)__bfloat16_as_ushort(l3) << 16);
    hi[i] = hw;
    lo[i] = lw;
}

// ---------------------------------------------------------------------------
// Transpose + split weights
// ---------------------------------------------------------------------------
__global__ __launch_bounds__(256) void transpose_split_kernel(
    const float* __restrict__ W, __nv_bfloat16* __restrict__ th, __nv_bfloat16* __restrict__ tl)
{
    __shared__ float t[32][33];
    int tx = threadIdx.x, ty = threadIdx.y;
    int n0 = blockIdx.x * 32, k0 = blockIdx.y * 32;
#pragma unroll
    for (int i = 0; i < 32; i += 8)
        t[ty + i][tx] = W[(size_t)(k0 + ty + i) * 1024 + n0 + tx];
    __syncthreads();
#pragma unroll
    for (int i = 0; i < 32; i += 8) {
        float v = t[tx][ty + i];
        __nv_bfloat16 h = __float2bfloat16(v);
        __nv_bfloat16 l = __float2bfloat16(v - __bfloat162float(h));
        size_t o = (size_t)(n0 + ty + i) * 1024 + k0 + tx;
        th[o] = h;
        tl[o] = l;
    }
}

// ---------------------------------------------------------------------------
// mma.sync split-bf16 GEMM (template epilogue):
//   OUTF32=1: C = acc + bias (fp32)
//   OUTF32=0: out = scale*(acc+bias) -> bf16 hi/lo pair
// ---------------------------------------------------------------------------
#define G_K     1024
#define G_N     1024
#define BKC     32
#define PAD_B   80
#define MAT_B   (128 * PAD_B)
#define OFF_AH  0
#define OFF_AL  (1 * MAT_B)
#define OFF_BH  (2 * MAT_B)
#define OFF_BL  (3 * MAT_B)
#define STAGE_B (4 * MAT_B)
#define GEMM_DSMEM (2 * STAGE_B)

__device__ __forceinline__ void gemm_load_stage(
    uint32_t sb, const __nv_bfloat16* __restrict__ Ah, const __nv_bfloat16* __restrict__ Al,
    const __nv_bfloat16* __restrict__ Bh, const __nv_bfloat16* __restrict__ Bl,
    int m0, int n0, int k0, int tid)
{
#pragma unroll
    for (int i = 0; i < 2; i++) {
        int idx = tid + i * 256;
        int r = idx >> 2, sg = idx & 3;
        uint32_t so = (uint32_t)(r * PAD_B + sg * 16);
        size_t ga = (size_t)(m0 + r) * G_K + k0 + sg * 8;
        size_t gb = (size_t)(n0 + r) * G_K + k0 + sg * 8;
        CP_ASYNC16(sb + OFF_AH + so, Ah + ga);
        CP_ASYNC16(sb + OFF_AL + so, Al + ga);
        CP_ASYNC16(sb + OFF_BH + so, Bh + gb);
        CP_ASYNC16(sb + OFF_BL + so, Bl + gb);
    }
}

template <int OUTF32>
__global__ __launch_bounds__(256) void gemm_mma_kernel(
    const __nv_bfloat16* __restrict__ Ah, const __nv_bfloat16* __restrict__ Al,
    const __nv_bfloat16* __restrict__ Bh, const __nv_bfloat16* __restrict__ Bl,
    const float* __restrict__ bias, float* __restrict__ Cf,
    __nv_bfloat16* __restrict__ Ch, __nv_bfloat16* __restrict__ Cl, float scale)
{
    extern __shared__ __align__(16) char dsm[];
    const uint32_t sm0 = smem_u32(dsm);
    const int tid = threadIdx.x;
    const int wid = tid >> 5;
    const int lane = tid & 31;
    const int wm = wid >> 2;
    const int wn = wid & 3;
    const int m0 = blockIdx.y * 128;
    const int n0 = blockIdx.x * 128;

    float acc[4][4][4];
#pragma unroll
    for (int i = 0; i < 4; i++)
#pragma unroll
        for (int j = 0; j < 4; j++)
#pragma unroll
            for (int c = 0; c < 4; c++) acc[i][j][c] = 0.0f;

    const int t4 = lane >> 3;
    const uint32_t a_lane_off = (uint32_t)(((lane & 7) + ((t4 & 1) << 3)) * PAD_B
                                           + ((t4 >> 1) << 3) * 2);
    const int li = lane & 15;
    const uint32_t b_lane_off = (uint32_t)((li & 7) * PAD_B + ((li >> 3) << 3) * 2);

    gemm_load_stage(sm0, Ah, Al, Bh, Bl, m0, n0, 0, tid);
    CP_ASYNC_COMMIT();

    const int NCH = G_K / BKC;
    for (int kc = 0; kc < NCH; kc++) {
        const uint32_t sb = sm0 + (kc & 1) * STAGE_B;
        if (kc + 1 < NCH) {
            gemm_load_stage(sm0 + ((kc + 1) & 1) * STAGE_B, Ah, Al, Bh, Bl,
                            m0, n0, (kc + 1) * BKC, tid);
            CP_ASYNC_COMMIT();
            CP_ASYNC_WAIT1();
        } else {
            CP_ASYNC_WAIT0();
        }
        __syncthreads();

#pragma unroll
        for (int ks = 0; ks < 2; ks++) {
            const uint32_t kb = (uint32_t)(ks * 16 * 2);
            uint32_t bh[4][2], bl[4][2];
#pragma unroll
            for (int nf = 0; nf < 4; nf++) {
                uint32_t base = (uint32_t)((wn * 32 + nf * 8) * PAD_B) + kb + b_lane_off;
                LDSM_X2(bh[nf][0], bh[nf][1], sb + OFF_BH + base);
                LDSM_X2(bl[nf][0], bl[nf][1], sb + OFF_BL + base);
            }
#pragma unroll
            for (int mf = 0; mf < 4; mf++) {
                uint32_t base = (uint32_t)((wm * 64 + mf * 16) * PAD_B) + kb + a_lane_off;
                uint32_t ah[4], al[4];
                LDSM_X4(ah[0], ah[1], ah[2], ah[3], sb + OFF_AH + base);
                LDSM_X4(al[0], al[1], al[2], al[3], sb + OFF_AL + base);
#pragma unroll
                for (int nf = 0; nf < 4; nf++) {
                    MMA_BF16(acc[mf][nf], ah, bh[nf]);
                    MMA_BF16(acc[mf][nf], ah, bl[nf]);
                    MMA_BF16(acc[mf][nf], al, bh[nf]);
                }
            }
        }
        __syncthreads();
    }

#pragma unroll
    for (int mf = 0; mf < 4; mf++) {
        int row0 = m0 + wm * 64 + mf * 16 + (lane >> 2);
#pragma unroll
        for (int nf = 0; nf < 4; nf++) {
            int col = n0 + wn * 32 + nf * 8 + ((lane & 3) << 1);
            float b0 = bias[col], b1 = bias[col + 1];
            if (OUTF32) {
                float2 v0 = make_float2(acc[mf][nf][0] + b0, acc[mf][nf][1] + b1);
                float2 v1 = make_float2(acc[mf][nf][2] + b0, acc[mf][nf][3] + b1);
                *(float2*)(Cf + (size_t)row0 * G_N + col) = v0;
                *(float2*)(Cf + (size_t)(row0 + 8) * G_N + col) = v1;
            } else {
                float o0 = scale * (acc[mf][nf][0] + b0);
                float o1 = scale * (acc[mf][nf][1] + b1);
                float o2 = scale * (acc[mf][nf][2] + b0);
                float o3 = scale * (acc[mf][nf][3] + b1);
                __nv_bfloat162 h0 = __float22bfloat162_rn(make_float2(o0, o1));
                float2 hf0 = __bfloat1622float2(h0);
                __nv_bfloat162 l0 = __float22bfloat162_rn(make_float2(o0 - hf0.x, o1 - hf0.y));
                __nv_bfloat162 h1 = __float22bfloat162_rn(make_float2(o2, o3));
                float2 hf1 = __bfloat1622float2(h1);
                __nv_bfloat162 l1 = __float22bfloat162_rn(make_float2(o2 - hf1.x, o3 - hf1.y));
                *(__nv_bfloat162*)(Ch + (size_t)row0 * G_N + col) = h0;
                *(__nv_bfloat162*)(Cl + (size_t)row0 * G_N + col) = l0;
                *(__nv_bfloat162*)(Ch + (size_t)(row0 + 8) * G_N + col) = h1;
                *(__nv_bfloat162*)(Cl + (size_t)(row0 + 8) * G_N + col) = l1;
            }
        }
    }
}

// ---------------------------------------------------------------------------
// Tensorized flash attention v2 (split-bf16 mma.sync, online softmax).
// Grid (S/128, NH, B), 256 threads / 8 warps; warp owns 16 q-rows.
// Q lives in a dedicated smem region (hi/lo); fragments are ldmatrix'd on the
// fly each tile, freeing 32 regs/thread -> 2 CTAs/SM for softmax/MMA overlap.
// Smem: Q 36864 + 2 KV stages (36864 each) = 110592 B/CTA.
// ---------------------------------------------------------------------------
#define AT_ROWB 144                     // bytes per padded row (72 bf16)
#define AT_MATB (64 * AT_ROWB)          // 9216 bytes per 64-row matrix
#define AT_STGB (4 * AT_MATB)           // Kh|Kl|Vh|Vl = 36864 per stage
#define AT_QB   (2 * 128 * AT_ROWB)     // Qh|Ql 128 rows = 36864
#define AT_KV0  AT_QB                   // KV stages start after Q
#define AT_DSMEM (AT_QB + 2 * AT_STGB)  // 110592

__device__ __forceinline__ void at_load_kv(
    uint32_t sb, const __nv_bfloat16* khb, const __nv_bfloat16* klb,
    const __nv_bfloat16* vhb, const __nv_bfloat16* vlb, int t0, int tid)
{
#pragma unroll
    for (int it = 0; it < 2; it++) {
        int id = tid + it * 256;
        int r = id >> 3, c = id & 7;
        uint32_t so = (uint32_t)(r * AT_ROWB + c * 16);
        size_t go = (size_t)(t0 + r) * ADIM + c * 8;
        CP_ASYNC16(sb + 0 * AT_MATB + so, khb + go);
        CP_ASYNC16(sb + 1 * AT_MATB + so, klb + go);
        CP_ASYNC16(sb + 2 * AT_MATB + so, vhb + go);
        CP_ASYNC16(sb + 3 * AT_MATB + so, vlb + go);
    }
}

__global__ __launch_bounds__(256, 2) void flash_mma_kernel(
    const __nv_bfloat16* __restrict__ qh, const __nv_bfloat16* __restrict__ ql,
    const __nv_bfloat16* __restrict__ kh, const __nv_bfloat16* __restrict__ kl,
    const __nv_bfloat16* __restrict__ vh, const __nv_bfloat16* __restrict__ vl,
    const int* __restrict__ mask,
    __nv_bfloat16* __restrict__ oh, __nv_bfloat16* __restrict__ ol)
{
    extern __shared__ __align__(16) char dsm[];
    const uint32_t sm0 = smem_u32(dsm);
    const int tid = threadIdx.x;
    const int w = tid >> 5;
    const int lane = tid & 31;
    const int s0 = blockIdx.x * 128;
    const int h = blockIdx.y;
    const int b = blockIdx.z;

    const __nv_bfloat16* qhb = qh + (size_t)(b * S_LEN + s0) * ADIM + h * HEADD;
    const __nv_bfloat16* qlb = ql + (size_t)(b * S_LEN + s0) * ADIM + h * HEADD;
    const __nv_bfloat16* khb = kh + (size_t)(b * T_LEN) * ADIM + h * HEADD;
    const __nv_bfloat16* klb = kl + (size_t)(b * T_LEN) * ADIM + h * HEADD;
    const __nv_bfloat16* vhb = vh + (size_t)(b * T_LEN) * ADIM + h * HEADD;
    const __nv_bfloat16* vlb = vl + (size_t)(b * T_LEN) * ADIM + h * HEADD;
    const int* mb = mask + (size_t)b * T_LEN;

    // --- Load Q tile (128x64 hi + lo) into dedicated region; prefetch KV0 ---
#pragma unroll
    for (int it = 0; it < 4; it++) {
        int id = tid + it * 256;
        int r = id >> 3, c = id & 7;
        uint32_t so = (uint32_t)(r * AT_ROWB + c * 16);
        size_t go = (size_t)r * ADIM + c * 8;
        CP_ASYNC16(sm0 + so, qhb + go);
        CP_ASYNC16(sm0 + 128 * AT_ROWB + so, qlb + go);
    }
    at_load_kv(sm0 + AT_KV0, khb, klb, vhb, vlb, 0, tid);
    CP_ASYNC_COMMIT();

    const int r8 = lane & 7;
    const int g = lane >> 3;
    // Per-warp Q ldmatrix base (row part); kf adds column offset.
    const uint32_t q_base = sm0 + (uint32_t)((w * 16 + r8 + (g & 1) * 8) * AT_ROWB
                                             + ((g >> 1) << 3) * 2);

    float oacc[8][4];
#pragma unroll
    for (int i = 0; i < 8; i++)
#pragma unroll
        for (int c = 0; c < 4; c++) oacc[i][c] = 0.0f;
    float mr0 = -1e30f, mr1 = -1e30f, lr0 = 0.0f, lr1 = 0.0f;

    const int c2 = (lane & 3) << 1;
    const int NT = T_LEN / 64;   // 32

    CP_ASYNC_WAIT0();
    __syncthreads();

    for (int tc = 0; tc < NT; tc++) {
        const uint32_t sb = sm0 + AT_KV0 + (tc & 1) * AT_STGB;
        if (tc + 1 < NT) {
            at_load_kv(sm0 + AT_KV0 + ((tc + 1) & 1) * AT_STGB, khb, klb, vhb, vlb,
                       (tc + 1) * 64, tid);
            CP_ASYNC_COMMIT();
        }

        // ---- S = Q K^T (split: qh*kh + qh*kl + ql*kh) ----
        float s[8][4];
#pragma unroll
        for (int i = 0; i < 8; i++)
#pragma unroll
            for (int c = 0; c < 4; c++) s[i][c] = 0.0f;

#pragma unroll
        for (int kf = 0; kf < 4; kf++) {
            uint32_t qa = q_base + (uint32_t)(16 * kf * 2);
            uint32_t qfh[4], qfl[4];
            LDSM_X4(qfh[0], qfh[1], qfh[2], qfh[3], qa);
            LDSM_X4(qfl[0], qfl[1], qfl[2], qfl[3], qa + 128 * AT_ROWB);
#pragma unroll
            for (int nfp = 0; nfp < 4; nfp++) {
                uint32_t addrK = sb + (uint32_t)((16 * nfp + r8 + (g & 1) * 8) * AT_ROWB
                                                 + (16 * kf + (g >> 1) * 8) * 2);
                uint32_t r0, r1, r2, r3, u0, u1, u2, u3;
                LDSM_X4(r0, r1, r2, r3, addrK);
                LDSM_X4(u0, u1, u2, u3, addrK + AT_MATB);
                uint32_t bh0[2] = {r0, r2}, bh1[2] = {r1, r3};
                uint32_t bl0[2] = {u0, u2}, bl1[2] = {u1, u3};
                MMA_BF16(s[2 * nfp],     qfh, bh0);
                MMA_BF16(s[2 * nfp],     qfh, bl0);
                MMA_BF16(s[2 * nfp],     qfl, bh0);
                MMA_BF16(s[2 * nfp + 1], qfh, bh1);
                MMA_BF16(s[2 * nfp + 1], qfh, bl1);
                MMA_BF16(s[2 * nfp + 1], qfl, bh1);
            }
        }

        // ---- mask + online softmax ----
        float mx0 = -1e30f, mx1 = -1e30f;
#pragma unroll
        for (int nf = 0; nf < 8; nf++) {
            int tcol = tc * 64 + nf * 8 + c2;
            int2 mm = *(const int2*)(mb + tcol);
            if (mm.x == 0) { s[nf][0] = -100000.0f; s[nf][2] = -100000.0f; }
            if (mm.y == 0) { s[nf][1] = -100000.0f; s[nf][3] = -100000.0f; }
            mx0 = fmaxf(mx0, fmaxf(s[nf][0], s[nf][1]));
            mx1 = fmaxf(mx1, fmaxf(s[nf][2], s[nf][3]));
        }
        mx0 = fmaxf(mx0, __shfl_xor_sync(0xffffffffu, mx0, 1));
        mx0 = fmaxf(mx0, __shfl_xor_sync(0xffffffffu, mx0, 2));
        mx1 = fmaxf(mx1, __shfl_xor_sync(0xffffffffu, mx1, 1));
        mx1 = fmaxf(mx1, __shfl_xor_sync(0xffffffffu, mx1, 2));

        float mn0 = fmaxf(mr0, mx0), mn1 = fmaxf(mr1, mx1);
        float al0 = __expf(mr0 - mn0), al1 = __expf(mr1 - mn1);
        float sum0 = 0.0f, sum1 = 0.0f;
#pragma unroll
        for (int nf = 0; nf < 8; nf++) {
            s[nf][0] = __expf(s[nf][0] - mn0);
            s[nf][1] = __expf(s[nf][1] - mn0);
            s[nf][2] = __expf(s[nf][2] - mn1);
            s[nf][3] = __expf(s[nf][3] - mn1);
            sum0 += s[nf][0] + s[nf][1];
            sum1 += s[nf][2] + s[nf][3];
        }
        sum0 += __shfl_xor_sync(0xffffffffu, sum0, 1);
        sum0 += __shfl_xor_sync(0xffffffffu, sum0, 2);
        sum1 += __shfl_xor_sync(0xffffffffu, sum1, 1);
        sum1 += __shfl_xor_sync(0xffffffffu, sum1, 2);
        lr0 = lr0 * al0 + sum0;
        lr1 = lr1 * al1 + sum1;
        mr0 = mn0;
        mr1 = mn1;
#pragma unroll
        for (int nf = 0; nf < 8; nf++) {
            oacc[nf][0] *= al0;
            oacc[nf][1] *= al0;
            oacc[nf][2] *= al1;
            oacc[nf][3] *= al1;
        }

        // ---- O += P V (split: ph*vh + ph*vl + pl*vh) ----
#pragma unroll
        for (int kf = 0; kf < 4; kf++) {
            uint32_t pah[4], pal[4];
#pragma unroll
            for (int q = 0; q < 2; q++) {
                const float* sp = s[2 * kf + q];
                __nv_bfloat162 h0 = __float22bfloat162_rn(make_float2(sp[0], sp[1]));
                float2 hf0 = __bfloat1622float2(h0);
                __nv_bfloat162 e0 = __float22bfloat162_rn(make_float2(sp[0] - hf0.x, sp[1] - hf0.y));
                __nv_bfloat162 h1 = __float22bfloat162_rn(make_float2(sp[2], sp[3]));
                float2 hf1 = __bfloat1622float2(h1);
                __nv_bfloat162 e1 = __float22bfloat162_rn(make_float2(sp[2] - hf1.x, sp[3] - hf1.y));
                pah[2 * q]     = *(uint32_t*)&h0;
                pah[2 * q + 1] = *(uint32_t*)&h1;
                pal[2 * q]     = *(uint32_t*)&e0;
                pal[2 * q + 1] = *(uint32_t*)&e1;
            }
#pragma unroll
            for (int nfp = 0; nfp < 4; nfp++) {
                uint32_t addrV = sb + 2 * AT_MATB
                               + (uint32_t)((16 * kf + r8 + (g & 1) * 8) * AT_ROWB
                                            + (16 * nfp + (g >> 1) * 8) * 2);
                uint32_t r0, r1, r2, r3, u0, u1, u2, u3;
                LDSM_X4_T(r0, r1, r2, r3, addrV);
                LDSM_X4_T(u0, u1, u2, u3, addrV + AT_MATB);
                uint32_t bvh0[2] = {r0, r1}, bvh1[2] = {r2, r3};
                uint32_t bvl0[2] = {u0, u1}, bvl1[2] = {u2, u3};
                MMA_BF16(oacc[2 * nfp],     pah, bvh0);
                MMA_BF16(oacc[2 * nfp],     pah, bvl0);
                MMA_BF16(oacc[2 * nfp],     pal, bvh0);
                MMA_BF16(oacc[2 * nfp + 1], pah, bvh1);
                MMA_BF16(oacc[2 * nfp + 1], pah, bvl1);
                MMA_BF16(oacc[2 * nfp + 1], pal, bvh1);
            }
        }

        if (tc + 1 < NT) CP_ASYNC_WAIT0();
        __syncthreads();   // all reads of sb done; next stage data visible
    }

    // ---- Normalize + write oh/ol ----
    float inv0 = 1.0f / lr0, inv1 = 1.0f / lr1;
    size_t row0 = (size_t)(b * S_LEN + s0 + w * 16 + (lane >> 2));
    size_t row1 = row0 + 8;
#pragma unroll
    for (int nf = 0; nf < 8; nf++) {
        int col = h * HEADD + nf * 8 + c2;
        float o0 = oacc[nf][0] * inv0, o1 = oacc[nf][1] * inv0;
        float o2 = oacc[nf][2] * inv1, o3 = oacc[nf][3] * inv1;
        __nv_bfloat162 h0 = __float22bfloat162_rn(make_float2(o0, o1));
        float2 hf0 = __bfloat1622float2(h0);
        __nv_bfloat162 e0 = __float22bfloat162_rn(make_float2(o0 - hf0.x, o1 - hf0.y));
        __nv_bfloat162 h1 = __float22bfloat162_rn(make_float2(o2, o3));
        float2 hf1 = __bfloat1622float2(h1);
        __nv_bfloat162 e1 = __float22bfloat162_rn(make_float2(o2 - hf1.x, o3 - hf1.y));
        *(__nv_bfloat162*)(oh + row0 * ADIM + col) = h0;
        *(__nv_bfloat162*)(ol + row0 * ADIM + col) = e0;
        *(__nv_bfloat162*)(oh + row1 * ADIM + col) = h1;
        *(__nv_bfloat162*)(ol + row1 * ADIM + col) = e1;
    }
}

// ---------------------------------------------------------------------------
// Launch
// ---------------------------------------------------------------------------
extern "C" void kernel_launch(void* const* d_in, const int* in_sizes, int n_in,
                              void* d_out, int out_size)
{
    const float* x  = (const float*)d_in[0];
    const float* y  = (const float*)d_in[1];
    const int*   mask = (const int*)d_in[2];
    const float* wq = (const float*)d_in[3];
    const float* bq = (const float*)d_in[4];
    const float* wk = (const float*)d_in[5];
    const float* bk = (const float*)d_in[6];
    const float* wv = (const float*)d_in[7];
    const float* bv = (const float*)d_in[8];
    const float* wo = (const float*)d_in[9];
    const float* bo = (const float*)d_in[10];
    float* out = (float*)d_out;

    __nv_bfloat16 *xh, *xl, *yh, *yl, *qhp, *qlp, *khp, *klp, *vhp, *vlp, *ohp, *olp;
    __nv_bfloat16 *wqh, *wql, *wkh, *wkl, *wvh, *wvl, *woh, *wol;
    cudaGetSymbolAddress((void**)&xh, g_xh);   cudaGetSymbolAddress((void**)&xl, g_xl);
    cudaGetSymbolAddress((void**)&yh, g_yh);   cudaGetSymbolAddress((void**)&yl, g_yl);
    cudaGetSymbolAddress((void**)&qhp, g_qh);  cudaGetSymbolAddress((void**)&qlp, g_ql);
    cudaGetSymbolAddress((void**)&khp, g_kh);  cudaGetSymbolAddress((void**)&klp, g_kl);
    cudaGetSymbolAddress((void**)&vhp, g_vh);  cudaGetSymbolAddress((void**)&vlp, g_vl);
    cudaGetSymbolAddress((void**)&ohp, g_oh);  cudaGetSymbolAddress((void**)&olp, g_ol);
    cudaGetSymbolAddress((void**)&wqh, g_wqh); cudaGetSymbolAddress((void**)&wql, g_wql);
    cudaGetSymbolAddress((void**)&wkh, g_wkh); cudaGetSymbolAddress((void**)&wkl, g_wkl);
    cudaGetSymbolAddress((void**)&wvh, g_wvh); cudaGetSymbolAddress((void**)&wvl, g_wvl);
    cudaGetSymbolAddress((void**)&woh, g_woh); cudaGetSymbolAddress((void**)&wol, g_wol);

    cudaFuncSetAttribute(gemm_mma_kernel<0>,
                         cudaFuncAttributeMaxDynamicSharedMemorySize, GEMM_DSMEM);
    cudaFuncSetAttribute(gemm_mma_kernel<1>,
                         cudaFuncAttributeMaxDynamicSharedMemorySize, GEMM_DSMEM);
    cudaFuncSetAttribute(flash_mma_kernel,
                         cudaFuncAttributeMaxDynamicSharedMemorySize, AT_DSMEM);

    const int n4_act = MROWS * HDIM / 4;

    // Split activations
    split_kernel<<<(n4_act + 255) / 256, 256>>>((const float4*)x, (uint2*)xh, (uint2*)xl, n4_act);
    split_kernel<<<(n4_act + 255) / 256, 256>>>((const float4*)y, (uint2*)yh, (uint2*)yl, n4_act);

    // Transpose + split weights
    dim3 tg(32, 32), tb(32, 8);
    transpose_split_kernel<<<tg, tb>>>(wq, wqh, wql);
    transpose_split_kernel<<<tg, tb>>>(wk, wkh, wkl);
    transpose_split_kernel<<<tg, tb>>>(wv, wvh, wvl);
    transpose_split_kernel<<<tg, tb>>>(wo, woh, wol);

    // QKV projections -> bf16 hi/lo (Q pre-scaled by 1/sqrt(64))
    dim3 gg(G_N / 128, MROWS / 128);
    gemm_mma_kernel<0><<<gg, 256, GEMM_DSMEM>>>(xh, xl, wqh, wql, bq, nullptr, qhp, qlp, 0.125f);
    gemm_mma_kernel<0><<<gg, 256, GEMM_DSMEM>>>(yh, yl, wkh, wkl, bk, nullptr, khp, klp, 1.0f);
    gemm_mma_kernel<0><<<gg, 256, GEMM_DSMEM>>>(yh, yl, wvh, wvl, bv, nullptr, vhp, vlp, 1.0f);

    // Tensorized flash attention -> oh/ol
    dim3 ga(S_LEN / 128, NHEAD, BB);
    flash_mma_kernel<<<ga, 256, AT_DSMEM>>>(qhp, qlp, khp, klp, vhp, vlp, mask, ohp, olp);

    // Output projection -> fp32 out
    gemm_mma_kernel<1><<<gg, 256, GEMM_DSMEM>>>(ohp, olp, woh, wol, bo, out, nullptr, nullptr, 1.0f);
}